// round 1
// baseline (speedup 1.0000x reference)
#include <cuda_runtime.h>
#include <cuda_bf16.h>
#include <math.h>

// ---------------- problem constants ----------------
#define B_   2
#define S_   2048
#define HID  2048
#define HKq  16
#define HVv  32
#define DKd  128
#define DVd  128
#define KC   4
#define CHUNK 64
#define NCH  (S_/CHUNK)          // 32
#define KEY_DIM 2048
#define VALUE_DIM 4096
#define CONV_DIM 8192
#define QKVZ_N 12288
#define BSz  (B_*S_)             // 4096
#define QSCALE 0.08838834764831845f   // DK^-0.5
#define SP 129                   // padded smem row stride for 128-wide tiles

// ---------------- scratch (static device memory; no allocations) ------------
__device__ float g_qkvz[(size_t)BSz*QKVZ_N];               // [BS,12288] q|k|v|z
__device__ float g_ba[(size_t)BSz*64];
__device__ float g_q[(size_t)B_*HKq*S_*DKd];               // [b,hq,s,d] scaled+l2n
__device__ float g_k[(size_t)B_*HKq*S_*DKd];               // l2n
__device__ float g_v[(size_t)B_*HVv*S_*DVd];
__device__ float g_g[(size_t)B_*HVv*S_];
__device__ float g_beta[(size_t)B_*HVv*S_];
__device__ float g_gc[(size_t)B_*HVv*S_];
__device__ float g_vadj[(size_t)B_*HVv*S_*DVd];
__device__ float g_kcd[(size_t)B_*HVv*S_*DKd];
__device__ float g_attn[(size_t)B_*HVv*S_*CHUNK];
__device__ float g_o[(size_t)BSz*VALUE_DIM];               // o, then gated o

// ---------------- generic fp32 SGEMM: C[M,N]=A[M,K]@B[K,N], all %128/%16 ----
__global__ void sgemm(const float* __restrict__ A, const float* __restrict__ Bm,
                      float* __restrict__ C, int M, int N, int K) {
    __shared__ float As[16][128];
    __shared__ float Bs[16][128];
    int tid = threadIdx.x;
    int bm = blockIdx.y, bn = blockIdx.x;
    const float* Ab = A + (size_t)bm * 128 * K;
    const float* Bb = Bm + (size_t)bn * 128;

    int arow = tid >> 2;              // 0..63
    int acol = (tid & 3) * 4;         // 0,4,8,12
    int brow = tid >> 5;              // 0..7
    int bcol = (tid & 31) * 4;
    int tx = tid & 15, ty = tid >> 4;

    float acc[8][8];
#pragma unroll
    for (int i = 0; i < 8; i++)
#pragma unroll
        for (int j = 0; j < 8; j++) acc[i][j] = 0.f;

    for (int k0 = 0; k0 < K; k0 += 16) {
        float4 a0 = *(const float4*)&Ab[(size_t)arow * K + k0 + acol];
        float4 a1 = *(const float4*)&Ab[(size_t)(arow + 64) * K + k0 + acol];
        As[acol + 0][arow] = a0.x; As[acol + 1][arow] = a0.y;
        As[acol + 2][arow] = a0.z; As[acol + 3][arow] = a0.w;
        As[acol + 0][arow + 64] = a1.x; As[acol + 1][arow + 64] = a1.y;
        As[acol + 2][arow + 64] = a1.z; As[acol + 3][arow + 64] = a1.w;
        float4 b0 = *(const float4*)&Bb[(size_t)(k0 + brow) * N + bcol];
        float4 b1 = *(const float4*)&Bb[(size_t)(k0 + brow + 8) * N + bcol];
        *(float4*)&Bs[brow][bcol] = b0;
        *(float4*)&Bs[brow + 8][bcol] = b1;
        __syncthreads();
#pragma unroll
        for (int kk = 0; kk < 16; kk++) {
            float ar[8], br[8];
            *(float4*)(ar)     = *(float4*)&As[kk][ty * 8];
            *(float4*)(ar + 4) = *(float4*)&As[kk][ty * 8 + 4];
            *(float4*)(br)     = *(float4*)&Bs[kk][tx * 8];
            *(float4*)(br + 4) = *(float4*)&Bs[kk][tx * 8 + 4];
#pragma unroll
            for (int i = 0; i < 8; i++)
#pragma unroll
                for (int j = 0; j < 8; j++) acc[i][j] += ar[i] * br[j];
        }
        __syncthreads();
    }
    float* Cb = C + (size_t)(bm * 128 + ty * 8) * N + bn * 128 + tx * 8;
#pragma unroll
    for (int i = 0; i < 8; i++) {
        *(float4*)&Cb[(size_t)i * N]     = make_float4(acc[i][0], acc[i][1], acc[i][2], acc[i][3]);
        *(float4*)&Cb[(size_t)i * N + 4] = make_float4(acc[i][4], acc[i][5], acc[i][6], acc[i][7]);
    }
}

// ---------------- BA projection: [BS,2048]@[2048,64] ----------------
__global__ void gemm_ba(const float* __restrict__ X, const float* __restrict__ W) {
    __shared__ float xs[16][64];
    int tid = threadIdx.x;
    int row0 = blockIdx.x * 16;
    int col = tid & 63;
    int rq = tid >> 6;                 // 0..3
    float acc[4] = {0.f, 0.f, 0.f, 0.f};
    for (int k0 = 0; k0 < HID; k0 += 64) {
        for (int i = tid; i < 16 * 64; i += 256) {
            int r = i >> 6, kk = i & 63;
            xs[r][kk] = X[(size_t)(row0 + r) * HID + k0 + kk];
        }
        __syncthreads();
        for (int kk = 0; kk < 64; kk++) {
            float w = W[(size_t)(k0 + kk) * 64 + col];
#pragma unroll
            for (int r = 0; r < 4; r++) acc[r] += xs[rq * 4 + r][kk] * w;
        }
        __syncthreads();
    }
#pragma unroll
    for (int r = 0; r < 4; r++) g_ba[(size_t)(row0 + rq * 4 + r) * 64 + col] = acc[r];
}

// -------- conv + silu + l2norm + head transpose + gates --------
__global__ void conv_gate(const float* __restrict__ cw, const float* __restrict__ dtb,
                          const float* __restrict__ Alog) {
    int bs = blockIdx.x;
    int b = bs / S_, s = bs % S_;
    int tid = threadIdx.x;
    __shared__ float cs[CONV_DIM];
    __shared__ float hsum[32];
    const float* base = g_qkvz + (size_t)bs * QKVZ_N;

    for (int c = tid; c < CONV_DIM; c += 256) {
        float w0 = cw[c*4+0], w1 = cw[c*4+1], w2 = cw[c*4+2], w3 = cw[c*4+3];
        float acc = base[c] * w3;
        if (s >= 1) acc += base[c - (size_t)QKVZ_N] * w2;
        if (s >= 2) acc += base[c - (size_t)2*QKVZ_N] * w1;
        if (s >= 3) acc += base[c - (size_t)3*QKVZ_N] * w0;
        cs[c] = acc / (1.f + __expf(-acc));           // silu
    }
    __syncthreads();
    int warp = tid >> 5, lane = tid & 31;
    for (int h = warp; h < 32; h += 8) {
        float ss = 0.f;
        for (int d = lane; d < 128; d += 32) { float v = cs[h*128 + d]; ss += v * v; }
#pragma unroll
        for (int o = 16; o; o >>= 1) ss += __shfl_xor_sync(~0u, ss, o);
        if (!lane) hsum[h] = rsqrtf(ss + 1e-6f);
    }
    __syncthreads();
    for (int c = tid; c < KEY_DIM; c += 256) {
        int h = c >> 7, d = c & 127;
        g_q[(((size_t)b*HKq + h)*S_ + s)*DKd + d] = cs[c] * hsum[h] * QSCALE;
    }
    for (int c = tid; c < KEY_DIM; c += 256) {
        int h = c >> 7, d = c & 127;
        g_k[(((size_t)b*HKq + h)*S_ + s)*DKd + d] = cs[KEY_DIM + c] * hsum[16 + h];
    }
    for (int c = tid; c < VALUE_DIM; c += 256) {
        int h = c >> 7, d = c & 127;
        g_v[(((size_t)b*HVv + h)*S_ + s)*DVd + d] = cs[2*KEY_DIM + c];
    }
    if (tid < 32) {
        float bb = g_ba[(size_t)bs*64 + tid];
        g_beta[((size_t)b*HVv + tid)*S_ + s] = 1.f / (1.f + expf(-bb));
    } else if (tid < 64) {
        int h = tid - 32;
        float a = g_ba[(size_t)bs*64 + 32 + h] + dtb[h];
        float sp = (a > 20.f) ? a : log1pf(expf(a));
        g_g[((size_t)b*HVv + h)*S_ + s] = -expf(Alog[h]) * sp;
    }
}

__device__ __forceinline__ float dot128(const float* a, const float* b) {
    float s0 = 0.f, s1 = 0.f, s2 = 0.f, s3 = 0.f;
#pragma unroll
    for (int d = 0; d < 128; d += 4) {
        s0 += a[d]   * b[d];
        s1 += a[d+1] * b[d+1];
        s2 += a[d+2] * b[d+2];
        s3 += a[d+3] * b[d+3];
    }
    return (s0 + s1) + (s2 + s3);
}

// -------- per-(b,h,chunk) intra-chunk quantities: A, T, v_adj, kcd, attn ----
__global__ void chunk_prep() {
    extern __shared__ float sm[];
    float* q_s  = sm;                      // 64*SP
    float* k_s  = q_s  + 64*SP;
    float* vb_s = k_s  + 64*SP;
    float* A_s  = vb_s + 64*SP;            // 64*64
    float* T_s  = A_s  + 64*64;            // 64*65
    __shared__ float gc_s[64], beta_s[64], kbe_s[64];

    int blk = blockIdx.x;
    int n = blk & 31, h = (blk >> 5) & 31, b = blk >> 10;
    int hq = h >> 1;
    int tid = threadIdx.x;

    size_t qk_off = (((size_t)b*HKq + hq)*S_ + (size_t)n*CHUNK) * DKd;
    size_t v_off  = (((size_t)b*HVv + h )*S_ + (size_t)n*CHUNK) * DVd;
    size_t gb_off = ((size_t)b*HVv + h)*S_ + (size_t)n*CHUNK;

    if (tid < 64) { gc_s[tid] = g_g[gb_off + tid]; beta_s[tid] = g_beta[gb_off + tid]; }
    __syncthreads();
    if (tid == 0) { for (int i = 1; i < 64; i++) gc_s[i] += gc_s[i - 1]; }
    __syncthreads();
    if (tid < 64) {
        g_gc[gb_off + tid] = gc_s[tid];
        kbe_s[tid] = beta_s[tid] * expf(gc_s[tid]);
    }
    for (int i = tid; i < 64 * 128; i += 256) {
        int r = i >> 7, d = i & 127;
        q_s [r*SP + d] = g_q[qk_off + i];
        k_s [r*SP + d] = g_k[qk_off + i];
        vb_s[r*SP + d] = g_v[v_off + i] * beta_s[r];
    }
    __syncthreads();

    // A[c][j] = beta[c] * (k[c].k[j]) * exp(gc[c]-gc[j]), strictly lower
    for (int i = tid; i < 4096; i += 256) {
        int c = i >> 6, j = i & 63;
        float val = 0.f;
        if (j < c)
            val = dot128(&k_s[c*SP], &k_s[j*SP]) * beta_s[c] * expf(gc_s[c] - gc_s[j]);
        A_s[i] = val;
    }
    __syncthreads();

    // T = (I+A)^{-1}, forward substitution, one thread per column
    if (tid < 64) {
        int col = tid;
        for (int c = 0; c < 64; c++) {
            float ssum = (c == col) ? 1.f : 0.f;
            for (int j = col; j < c; j++) ssum -= A_s[c*64 + j] * T_s[j*65 + col];
            T_s[c*65 + col] = (c >= col) ? ssum : 0.f;
        }
    }
    __syncthreads();

    // v_adj = T @ v_beta ; kcd = T @ (k_beta*exp(gc))
    size_t kcd_off = (((size_t)b*HVv + h)*S_ + (size_t)n*CHUNK) * DKd;
    for (int i = tid; i < 64 * 128; i += 256) {
        int c = i >> 7, d = i & 127;
        float av = 0.f, ak = 0.f;
#pragma unroll 4
        for (int j = 0; j <= c; j++) {
            float t = T_s[c*65 + j];
            av += t * vb_s[j*SP + d];
            ak += t * k_s[j*SP + d] * kbe_s[j];
        }
        g_vadj[v_off + i]  = av;
        g_kcd [kcd_off + i] = ak;
    }
    // attn_local[c][j] = (q[c].k[j]) * exp(gc[c]-gc[j]) for j<=c
    size_t at_off = gb_off * CHUNK;
    for (int i = tid; i < 4096; i += 256) {
        int c = i >> 6, j = i & 63;
        float val = 0.f;
        if (j <= c)
            val = dot128(&q_s[c*SP], &k_s[j*SP]) * expf(gc_s[c] - gc_s[j]);
        g_attn[at_off + i] = val;
    }
}

// -------- sequential scan over chunks; grid (bh=64, dv_tile=4) --------
__global__ void scan_kernel() {
    extern __shared__ float sm[];
    float* q_s    = sm;                    // 64*SP
    float* k_s    = q_s   + 64*SP;
    float* kcd_s  = k_s   + 64*SP;
    float* attn_s = kcd_s + 64*SP;         // 4096
    float* vadj_s = attn_s + 4096;         // 2048
    float* vnew_s = vadj_s + 2048;         // 2048
    float* st     = vnew_s + 2048;         // 128*32
    __shared__ float gc_s[64], eg_s[64], ek_s[64];

    int bh = blockIdx.x, dvt = blockIdx.y;
    int b = bh >> 5, h = bh & 31, hq = h >> 1;
    int tid = threadIdx.x;
    int dv = tid & 31, part = tid >> 5;    // part 0..7

    for (int i = tid; i < 128 * 32; i += 256) st[i] = 0.f;

    for (int n = 0; n < NCH; n++) {
        size_t qk_off = (((size_t)b*HKq + hq)*S_ + (size_t)n*CHUNK) * DKd;
        size_t kv_off = (((size_t)b*HVv + h )*S_ + (size_t)n*CHUNK) * DKd;
        size_t gb_off = ((size_t)b*HVv + h)*S_ + (size_t)n*CHUNK;
        __syncthreads();
        for (int i = tid; i < 64 * 128; i += 256) {
            int r = i >> 7, d = i & 127;
            q_s  [r*SP + d] = g_q  [qk_off + i];
            k_s  [r*SP + d] = g_k  [qk_off + i];
            kcd_s[r*SP + d] = g_kcd[kv_off + i];
        }
        for (int i = tid; i < 4096; i += 256) attn_s[i] = g_attn[gb_off*CHUNK + i];
        for (int i = tid; i < 2048; i += 256) {
            int c = i >> 5, d = i & 31;
            vadj_s[i] = g_vadj[kv_off + (size_t)c*128 + dvt*32 + d];
        }
        if (tid < 64) { float gv = g_gc[gb_off + tid]; gc_s[tid] = gv; eg_s[tid] = expf(gv); }
        __syncthreads();
        if (tid < 64) ek_s[tid] = expf(gc_s[63] - gc_s[tid]);

        // v_new = v_adj - kcd @ state
        float acc[8];
#pragma unroll
        for (int ii = 0; ii < 8; ii++) acc[ii] = vadj_s[(part + ii*8)*32 + dv];
        for (int dk = 0; dk < 128; dk++) {
            float sv = st[dk*32 + dv];
#pragma unroll
            for (int ii = 0; ii < 8; ii++) acc[ii] -= kcd_s[(part + ii*8)*SP + dk] * sv;
        }
#pragma unroll
        for (int ii = 0; ii < 8; ii++) vnew_s[(part + ii*8)*32 + dv] = acc[ii];
        __syncthreads();

        // o = (q*exp(gc)) @ state + attn @ v_new
        float oc[8];
#pragma unroll
        for (int ii = 0; ii < 8; ii++) oc[ii] = 0.f;
        for (int dk = 0; dk < 128; dk++) {
            float sv = st[dk*32 + dv];
#pragma unroll
            for (int ii = 0; ii < 8; ii++) oc[ii] += q_s[(part + ii*8)*SP + dk] * sv;
        }
#pragma unroll
        for (int ii = 0; ii < 8; ii++) oc[ii] *= eg_s[part + ii*8];
        for (int j = 0; j < 64; j++) {
            float vv = vnew_s[j*32 + dv];
#pragma unroll
            for (int ii = 0; ii < 8; ii++) oc[ii] += attn_s[(part + ii*8)*64 + j] * vv;
        }
        size_t o_base = ((size_t)b*S_ + (size_t)n*CHUNK) * VALUE_DIM + (size_t)h*DVd + dvt*32 + dv;
#pragma unroll
        for (int ii = 0; ii < 8; ii++)
            g_o[o_base + (size_t)(part + ii*8) * VALUE_DIM] = oc[ii];
        __syncthreads();

        // state = state*exp(g_last) + (k*exp(g_last-gc))^T @ v_new
        float egl = eg_s[63];
        float sa[16];
#pragma unroll
        for (int ii = 0; ii < 16; ii++) sa[ii] = st[(part + ii*8)*32 + dv] * egl;
        for (int c = 0; c < 64; c++) {
            float vv = vnew_s[c*32 + dv] * ek_s[c];
#pragma unroll
            for (int ii = 0; ii < 16; ii++) sa[ii] += k_s[c*SP + (part + ii*8)] * vv;
        }
#pragma unroll
        for (int ii = 0; ii < 16; ii++) st[(part + ii*8)*32 + dv] = sa[ii];
    }
}

// -------- gated RMSNorm: o = rmsnorm(o)*w*silu(z) (in place) --------
__global__ void gated_norm(const float* __restrict__ nw) {
    int bs = blockIdx.x;
    int warp = threadIdx.x >> 5, lane = threadIdx.x & 31;
    for (int h = warp; h < HVv; h += 8) {
        size_t off = (size_t)bs * VALUE_DIM + (size_t)h * DVd;
        float4 v = ((float4*)(g_o + off))[lane];
        float ss = v.x*v.x + v.y*v.y + v.z*v.z + v.w*v.w;
#pragma unroll
        for (int o = 16; o; o >>= 1) ss += __shfl_xor_sync(~0u, ss, o);
        float r = rsqrtf(ss / 128.f + 1e-6f);
        size_t zoff = (size_t)bs * QKVZ_N + 2*KEY_DIM + VALUE_DIM + (size_t)h * DVd;
        float4 z = ((const float4*)(g_qkvz + zoff))[lane];
        float4 w = ((const float4*)nw)[lane];
        v.x = v.x * r * w.x * (z.x / (1.f + expf(-z.x)));
        v.y = v.y * r * w.y * (z.y / (1.f + expf(-z.y)));
        v.z = v.z * r * w.z * (z.z / (1.f + expf(-z.z)));
        v.w = v.w * r * w.w * (z.w / (1.f + expf(-z.w)));
        ((float4*)(g_o + off))[lane] = v;
    }
}

// ---------------- launcher ----------------
extern "C" void kernel_launch(void* const* d_in, const int* in_sizes, int n_in,
                              void* d_out, int out_size) {
    const float* hidden = (const float*)d_in[0];
    const float* Wqkvz  = (const float*)d_in[1];
    const float* Wba    = (const float*)d_in[2];
    const float* convw  = (const float*)d_in[3];
    const float* dtb    = (const float*)d_in[4];
    const float* Alog   = (const float*)d_in[5];
    const float* nw     = (const float*)d_in[6];
    const float* Wout   = (const float*)d_in[7];
    float* out = (float*)d_out;

    float *qkvz_p, *o_p;
    cudaGetSymbolAddress((void**)&qkvz_p, g_qkvz);
    cudaGetSymbolAddress((void**)&o_p, g_o);

    const int SMEM3 = (3*64*SP + 64*64 + 64*65) * 4;   // 132096 B
    const int SMEM4 = (3*64*SP + 4096 + 2048 + 2048 + 128*32) * 4;  // 148224 B
    cudaFuncSetAttribute(chunk_prep, cudaFuncAttributeMaxDynamicSharedMemorySize, SMEM3);
    cudaFuncSetAttribute(scan_kernel, cudaFuncAttributeMaxDynamicSharedMemorySize, SMEM4);

    // 1) qkvz projection
    sgemm<<<dim3(QKVZ_N/128, BSz/128), 256>>>(hidden, Wqkvz, qkvz_p, BSz, QKVZ_N, HID);
    // 2) ba projection
    gemm_ba<<<BSz/16, 256>>>(hidden, Wba);
    // 3) conv + silu + l2norm + gates
    conv_gate<<<BSz, 256>>>(convw, dtb, Alog);
    // 4) per-chunk prep
    chunk_prep<<<B_*HVv*NCH, 256, SMEM3>>>();
    // 5) sequential scan
    scan_kernel<<<dim3(B_*HVv, 4), 256, SMEM4>>>();
    // 6) gated rmsnorm
    gated_norm<<<BSz, 256>>>(nw);
    // 7) output projection
    sgemm<<<dim3(HID/128, BSz/128), 256>>>(o_p, Wout, out, BSz, HID, VALUE_DIM);
}

// round 3
// speedup vs baseline: 1.6180x; 1.6180x over previous
#include <cuda_runtime.h>
#include <cuda_bf16.h>
#include <math.h>
#include <stdint.h>

// ---------------- problem constants ----------------
#define B_   2
#define S_   2048
#define HID  2048
#define HKq  16
#define HVv  32
#define DKd  128
#define DVd  128
#define KC   4
#define CHUNK 64
#define NCH  (S_/CHUNK)          // 32
#define KEY_DIM 2048
#define VALUE_DIM 4096
#define CONV_DIM 8192
#define QKVZ_N 12288
#define BSz  (B_*S_)             // 4096
#define QSCALE 0.08838834764831845f   // DK^-0.5
#define SP 129                   // padded smem row stride for 128-wide fp32 tiles

// ---------------- scratch (static device memory; no allocations) ------------
__device__ float g_qkvz[(size_t)BSz*QKVZ_N];               // [BS,12288] q|k|v|z
__device__ float g_ba[(size_t)BSz*64];
__device__ float g_q[(size_t)B_*HKq*S_*DKd];
__device__ float g_k[(size_t)B_*HKq*S_*DKd];
__device__ float g_v[(size_t)B_*HVv*S_*DVd];
__device__ float g_g[(size_t)B_*HVv*S_];
__device__ float g_beta[(size_t)B_*HVv*S_];
__device__ float g_gc[(size_t)B_*HVv*S_];
__device__ float g_vadj[(size_t)B_*HVv*S_*DVd];
__device__ float g_kcd[(size_t)B_*HVv*S_*DKd];
__device__ float g_attn[(size_t)B_*HVv*S_*CHUNK];
__device__ float g_o[(size_t)BSz*VALUE_DIM];

// bf16 split-precision operand buffers (reused across the two GEMMs)
__device__ __nv_bfloat16 g_p [(size_t)8388608];    // A1 hi  / B2t hi
__device__ __nv_bfloat16 g_q2[(size_t)8388608];    // A1 lo  / B2t lo
__device__ __nv_bfloat16 g_r [(size_t)25165824];   // B1t hi / A2 hi
__device__ __nv_bfloat16 g_s2[(size_t)25165824];   // B1t lo / A2 lo

__device__ __forceinline__ uint32_t smem_u32(const void* p) {
    uint32_t a;
    asm("{ .reg .u64 t; cvta.to.shared.u64 t, %1; cvt.u32.u64 %0, t; }" : "=r"(a) : "l"(p));
    return a;
}

// ---------------- fp32 -> bf16 hi/lo split (elementwise, float4) ----------------
__global__ void cvt_split(const float* __restrict__ X, __nv_bfloat16* __restrict__ H,
                          __nv_bfloat16* __restrict__ L) {
    size_t i = ((size_t)blockIdx.x * 256 + threadIdx.x) * 4;
    float4 v = *(const float4*)&X[i];
    __nv_bfloat16 h0 = __float2bfloat16(v.x), h1 = __float2bfloat16(v.y);
    __nv_bfloat16 h2 = __float2bfloat16(v.z), h3 = __float2bfloat16(v.w);
    __nv_bfloat16 l0 = __float2bfloat16(v.x - __bfloat162float(h0));
    __nv_bfloat16 l1 = __float2bfloat16(v.y - __bfloat162float(h1));
    __nv_bfloat16 l2 = __float2bfloat16(v.z - __bfloat162float(h2));
    __nv_bfloat16 l3 = __float2bfloat16(v.w - __bfloat162float(h3));
    ushort4 hv, lv;
    hv.x = *(unsigned short*)&h0; hv.y = *(unsigned short*)&h1;
    hv.z = *(unsigned short*)&h2; hv.w = *(unsigned short*)&h3;
    lv.x = *(unsigned short*)&l0; lv.y = *(unsigned short*)&l1;
    lv.z = *(unsigned short*)&l2; lv.w = *(unsigned short*)&l3;
    *(ushort4*)&H[i] = hv;
    *(ushort4*)&L[i] = lv;
}

// ---------------- fp32 [K,N] -> bf16 hi/lo [N,K] transpose split ----------------
__global__ void cvt_split_T(const float* __restrict__ W, __nv_bfloat16* __restrict__ Ht,
                            __nv_bfloat16* __restrict__ Lt, int K, int N) {
    __shared__ float tile[32][33];
    int n0 = blockIdx.x * 32, k0 = blockIdx.y * 32;
    int tx = threadIdx.x, ty = threadIdx.y;   // 32 x 8
#pragma unroll
    for (int j = 0; j < 32; j += 8)
        tile[ty + j][tx] = W[(size_t)(k0 + ty + j) * N + n0 + tx];
    __syncthreads();
#pragma unroll
    for (int j = 0; j < 32; j += 8) {
        float v = tile[tx][ty + j];
        __nv_bfloat16 h = __float2bfloat16(v);
        __nv_bfloat16 l = __float2bfloat16(v - __bfloat162float(h));
        size_t o = (size_t)(n0 + ty + j) * K + k0 + tx;
        Ht[o] = h; Lt[o] = l;
    }
}

// ============ split-bf16 HMMA GEMM: C[M,N] = A[M,K] @ Bt[N,K]^T ============
// mma.sync m16n8k16 bf16, fp32 accum; 128x128 CTA tile, BK=32, 3-stage cp.async.
#define PS 40                     // padded bf16 row stride (conflict-free ldmatrix)
#define TEN_SZ (128*PS)           // elements per tensor tile (5120)
#define STG_SZ (4*TEN_SZ)         // elements per stage (Ah|Al|Bh|Bl)

__device__ __forceinline__ void mma_bf16(float* c, const uint32_t* a, const uint32_t* b) {
    asm volatile("mma.sync.aligned.m16n8k16.row.col.f32.bf16.bf16.f32 "
                 "{%0,%1,%2,%3}, {%4,%5,%6,%7}, {%8,%9}, {%0,%1,%2,%3};"
                 : "+f"(c[0]), "+f"(c[1]), "+f"(c[2]), "+f"(c[3])
                 : "r"(a[0]), "r"(a[1]), "r"(a[2]), "r"(a[3]), "r"(b[0]), "r"(b[1]));
}
__device__ __forceinline__ void ldmx4(uint32_t* r, uint32_t addr) {
    asm volatile("ldmatrix.sync.aligned.m8n8.x4.shared.b16 {%0,%1,%2,%3}, [%4];"
                 : "=r"(r[0]), "=r"(r[1]), "=r"(r[2]), "=r"(r[3]) : "r"(addr));
}

__device__ __forceinline__ void stage_load(uint32_t sbase_b, int stage,
    const __nv_bfloat16* a0, const __nv_bfloat16* a1,
    const __nv_bfloat16* b0, const __nv_bfloat16* b1,
    int K, int kt, int tid)
{
    const __nv_bfloat16* gp[4] = {a0, a1, b0, b1};
    uint32_t st_b = sbase_b + (uint32_t)stage * (STG_SZ * 2);
#pragma unroll
    for (int t = 0; t < 4; t++) {
        uint32_t tb = st_b + (uint32_t)t * (TEN_SZ * 2);
#pragma unroll
        for (int j = 0; j < 2; j++) {
            int idx = j * 256 + tid;
            int row = idx >> 2, c16 = idx & 3;
            uint32_t sa = tb + (uint32_t)(row * (PS*2) + c16 * 16);
            const void* ga = gp[t] + (size_t)row * K + (size_t)kt * 32 + c16 * 8;
            asm volatile("cp.async.cg.shared.global [%0], [%1], 16;" :: "r"(sa), "l"(ga));
        }
    }
    asm volatile("cp.async.commit_group;" ::: "memory");
}

__global__ void __launch_bounds__(256, 1) mmgemm(
    const __nv_bfloat16* __restrict__ Ah, const __nv_bfloat16* __restrict__ Al,
    const __nv_bfloat16* __restrict__ Bh, const __nv_bfloat16* __restrict__ Bl,
    float* __restrict__ C, int M, int N, int K)
{
    extern __shared__ __nv_bfloat16 smem[];
    uint32_t sbase = smem_u32(smem);
    int tid = threadIdx.x, lane = tid & 31, wid = tid >> 5;
    int warpM = wid >> 2, warpN = wid & 3;      // 2 x 4 warp grid
    int bn = blockIdx.x, bm = blockIdx.y;
    const int T = K >> 5;

    const __nv_bfloat16* a0 = Ah + (size_t)bm * 128 * K;
    const __nv_bfloat16* a1 = Al + (size_t)bm * 128 * K;
    const __nv_bfloat16* b0 = Bh + (size_t)bn * 128 * K;
    const __nv_bfloat16* b1 = Bl + (size_t)bn * 128 * K;

    // ldmatrix per-lane element offsets (in bf16 elements)
    int g = lane >> 3, lr = lane & 7;
    uint32_t aoff = (uint32_t)((warpM*64 + (g&1)*8 + lr) * PS + (g>>1)*8);
    uint32_t boff = (uint32_t)((warpN*32 + (g>>1)*8 + lr) * PS + (g&1)*8);

    float acc[4][4][4];
#pragma unroll
    for (int i = 0; i < 4; i++)
#pragma unroll
        for (int j = 0; j < 4; j++)
#pragma unroll
            for (int r = 0; r < 4; r++) acc[i][j][r] = 0.f;

    stage_load(sbase, 0, a0, a1, b0, b1, K, 0, tid);
    stage_load(sbase, 1, a0, a1, b0, b1, K, 1, tid);

    for (int kt = 0; kt < T; kt++) {
        if (kt + 1 < T) asm volatile("cp.async.wait_group 1;" ::: "memory");
        else            asm volatile("cp.async.wait_group 0;" ::: "memory");
        __syncthreads();
        if (kt + 2 < T) stage_load(sbase, (kt + 2) % 3, a0, a1, b0, b1, K, kt + 2, tid);

        uint32_t st = sbase + (uint32_t)(kt % 3) * (STG_SZ * 2);
        uint32_t sAh = st, sAl = st + TEN_SZ*2, sBh = st + 2*TEN_SZ*2, sBl = st + 3*TEN_SZ*2;
#pragma unroll
        for (int ks = 0; ks < 2; ks++) {
            int kk = ks * 16;
            uint32_t ah[4][4], al[4][4], bh[4][2], bl[4][2];
#pragma unroll
            for (int mi = 0; mi < 4; mi++) {
                uint32_t off = (aoff + mi*16*PS + kk) * 2;
                ldmx4(ah[mi], sAh + off);
                ldmx4(al[mi], sAl + off);
            }
#pragma unroll
            for (int p = 0; p < 2; p++) {
                uint32_t off = (boff + p*16*PS + kk) * 2;
                uint32_t rh[4], rl[4];
                ldmx4(rh, sBh + off);
                ldmx4(rl, sBl + off);
                bh[2*p][0] = rh[0]; bh[2*p][1] = rh[1];
                bh[2*p+1][0] = rh[2]; bh[2*p+1][1] = rh[3];
                bl[2*p][0] = rl[0]; bl[2*p][1] = rl[1];
                bl[2*p+1][0] = rl[2]; bl[2*p+1][1] = rl[3];
            }
#pragma unroll
            for (int mi = 0; mi < 4; mi++)
#pragma unroll
                for (int ni = 0; ni < 4; ni++) {
                    mma_bf16(acc[mi][ni], ah[mi], bh[ni]);
                    mma_bf16(acc[mi][ni], ah[mi], bl[ni]);
                    mma_bf16(acc[mi][ni], al[mi], bh[ni]);
                }
        }
        __syncthreads();
    }

    // epilogue: fragment -> C
    int rr = lane >> 2, cc = (lane & 3) * 2;
#pragma unroll
    for (int mi = 0; mi < 4; mi++) {
        int row0 = bm * 128 + warpM * 64 + mi * 16 + rr;
#pragma unroll
        for (int ni = 0; ni < 4; ni++) {
            int col = bn * 128 + warpN * 32 + ni * 8 + cc;
            float2 v0 = make_float2(acc[mi][ni][0], acc[mi][ni][1]);
            float2 v1 = make_float2(acc[mi][ni][2], acc[mi][ni][3]);
            *(float2*)&C[(size_t)row0 * N + col]       = v0;
            *(float2*)&C[(size_t)(row0 + 8) * N + col] = v1;
        }
    }
}

// ---------------- BA projection: [BS,2048]@[2048,64] ----------------
__global__ void gemm_ba(const float* __restrict__ X, const float* __restrict__ W) {
    __shared__ float xs[16][64];
    int tid = threadIdx.x;
    int row0 = blockIdx.x * 16;
    int col = tid & 63;
    int rq = tid >> 6;
    float acc[4] = {0.f, 0.f, 0.f, 0.f};
    for (int k0 = 0; k0 < HID; k0 += 64) {
        for (int i = tid; i < 16 * 64; i += 256) {
            int r = i >> 6, kk = i & 63;
            xs[r][kk] = X[(size_t)(row0 + r) * HID + k0 + kk];
        }
        __syncthreads();
        for (int kk = 0; kk < 64; kk++) {
            float w = W[(size_t)(k0 + kk) * 64 + col];
#pragma unroll
            for (int r = 0; r < 4; r++) acc[r] += xs[rq * 4 + r][kk] * w;
        }
        __syncthreads();
    }
#pragma unroll
    for (int r = 0; r < 4; r++) g_ba[(size_t)(row0 + rq * 4 + r) * 64 + col] = acc[r];
}

// -------- conv + silu + l2norm + head transpose + gates --------
__global__ void conv_gate(const float* __restrict__ cw, const float* __restrict__ dtb,
                          const float* __restrict__ Alog) {
    int bs = blockIdx.x;
    int b = bs / S_, s = bs % S_;
    int tid = threadIdx.x;
    __shared__ float cs[CONV_DIM];
    __shared__ float hsum[32];
    const float* base = g_qkvz + (size_t)bs * QKVZ_N;

    for (int c = tid; c < CONV_DIM; c += 256) {
        float w0 = cw[c*4+0], w1 = cw[c*4+1], w2 = cw[c*4+2], w3 = cw[c*4+3];
        float acc = base[c] * w3;
        if (s >= 1) acc += base[c - (size_t)QKVZ_N] * w2;
        if (s >= 2) acc += base[c - (size_t)2*QKVZ_N] * w1;
        if (s >= 3) acc += base[c - (size_t)3*QKVZ_N] * w0;
        cs[c] = acc / (1.f + __expf(-acc));
    }
    __syncthreads();
    int warp = tid >> 5, lane = tid & 31;
    for (int h = warp; h < 32; h += 8) {
        float ss = 0.f;
        for (int d = lane; d < 128; d += 32) { float v = cs[h*128 + d]; ss += v * v; }
#pragma unroll
        for (int o = 16; o; o >>= 1) ss += __shfl_xor_sync(~0u, ss, o);
        if (!lane) hsum[h] = rsqrtf(ss + 1e-6f);
    }
    __syncthreads();
    for (int c = tid; c < KEY_DIM; c += 256) {
        int h = c >> 7, d = c & 127;
        g_q[(((size_t)b*HKq + h)*S_ + s)*DKd + d] = cs[c] * hsum[h] * QSCALE;
    }
    for (int c = tid; c < KEY_DIM; c += 256) {
        int h = c >> 7, d = c & 127;
        g_k[(((size_t)b*HKq + h)*S_ + s)*DKd + d] = cs[KEY_DIM + c] * hsum[16 + h];
    }
    for (int c = tid; c < VALUE_DIM; c += 256) {
        int h = c >> 7, d = c & 127;
        g_v[(((size_t)b*HVv + h)*S_ + s)*DVd + d] = cs[2*KEY_DIM + c];
    }
    if (tid < 32) {
        float bb = g_ba[(size_t)bs*64 + tid];
        g_beta[((size_t)b*HVv + tid)*S_ + s] = 1.f / (1.f + expf(-bb));
    } else if (tid < 64) {
        int h = tid - 32;
        float a = g_ba[(size_t)bs*64 + 32 + h] + dtb[h];
        float sp = (a > 20.f) ? a : log1pf(expf(a));
        g_g[((size_t)b*HVv + h)*S_ + s] = -expf(Alog[h]) * sp;
    }
}

__device__ __forceinline__ float dot128(const float* a, const float* b) {
    float s0 = 0.f, s1 = 0.f, s2 = 0.f, s3 = 0.f;
#pragma unroll
    for (int d = 0; d < 128; d += 4) {
        s0 += a[d]   * b[d];
        s1 += a[d+1] * b[d+1];
        s2 += a[d+2] * b[d+2];
        s3 += a[d+3] * b[d+3];
    }
    return (s0 + s1) + (s2 + s3);
}

// -------- per-(b,h,chunk) intra-chunk quantities --------
__global__ void chunk_prep() {
    extern __shared__ float sm[];
    float* q_s  = sm;
    float* k_s  = q_s  + 64*SP;
    float* vb_s = k_s  + 64*SP;
    float* A_s  = vb_s + 64*SP;
    float* T_s  = A_s  + 64*64;
    __shared__ float gc_s[64], beta_s[64], kbe_s[64];

    int blk = blockIdx.x;
    int n = blk & 31, h = (blk >> 5) & 31, b = blk >> 10;
    int hq = h >> 1;
    int tid = threadIdx.x;

    size_t qk_off = (((size_t)b*HKq + hq)*S_ + (size_t)n*CHUNK) * DKd;
    size_t v_off  = (((size_t)b*HVv + h )*S_ + (size_t)n*CHUNK) * DVd;
    size_t gb_off = ((size_t)b*HVv + h)*S_ + (size_t)n*CHUNK;

    if (tid < 64) { gc_s[tid] = g_g[gb_off + tid]; beta_s[tid] = g_beta[gb_off + tid]; }
    __syncthreads();
    if (tid == 0) { for (int i = 1; i < 64; i++) gc_s[i] += gc_s[i - 1]; }
    __syncthreads();
    if (tid < 64) {
        g_gc[gb_off + tid] = gc_s[tid];
        kbe_s[tid] = beta_s[tid] * expf(gc_s[tid]);
    }
    for (int i = tid; i < 64 * 128; i += 256) {
        int r = i >> 7, d = i & 127;
        q_s [r*SP + d] = g_q[qk_off + i];
        k_s [r*SP + d] = g_k[qk_off + i];
        vb_s[r*SP + d] = g_v[v_off + i] * beta_s[r];
    }
    __syncthreads();

    for (int i = tid; i < 4096; i += 256) {
        int c = i >> 6, j = i & 63;
        float val = 0.f;
        if (j < c)
            val = dot128(&k_s[c*SP], &k_s[j*SP]) * beta_s[c] * expf(gc_s[c] - gc_s[j]);
        A_s[i] = val;
    }
    __syncthreads();

    if (tid < 64) {
        int col = tid;
        for (int c = 0; c < 64; c++) {
            float ssum = (c == col) ? 1.f : 0.f;
            for (int j = col; j < c; j++) ssum -= A_s[c*64 + j] * T_s[j*65 + col];
            T_s[c*65 + col] = (c >= col) ? ssum : 0.f;
        }
    }
    __syncthreads();

    size_t kcd_off = (((size_t)b*HVv + h)*S_ + (size_t)n*CHUNK) * DKd;
    for (int i = tid; i < 64 * 128; i += 256) {
        int c = i >> 7, d = i & 127;
        float av = 0.f, ak = 0.f;
#pragma unroll 4
        for (int j = 0; j <= c; j++) {
            float t = T_s[c*65 + j];
            av += t * vb_s[j*SP + d];
            ak += t * k_s[j*SP + d] * kbe_s[j];
        }
        g_vadj[v_off + i]  = av;
        g_kcd [kcd_off + i] = ak;
    }
    size_t at_off = gb_off * CHUNK;
    for (int i = tid; i < 4096; i += 256) {
        int c = i >> 6, j = i & 63;
        float val = 0.f;
        if (j <= c)
            val = dot128(&q_s[c*SP], &k_s[j*SP]) * expf(gc_s[c] - gc_s[j]);
        g_attn[at_off + i] = val;
    }
}

// -------- sequential scan over chunks --------
__global__ void scan_kernel() {
    extern __shared__ float sm[];
    float* q_s    = sm;
    float* k_s    = q_s   + 64*SP;
    float* kcd_s  = k_s   + 64*SP;
    float* attn_s = kcd_s + 64*SP;
    float* vadj_s = attn_s + 4096;
    float* vnew_s = vadj_s + 2048;
    float* st     = vnew_s + 2048;
    __shared__ float gc_s[64], eg_s[64], ek_s[64];

    int bh = blockIdx.x, dvt = blockIdx.y;
    int b = bh >> 5, h = bh & 31, hq = h >> 1;
    int tid = threadIdx.x;
    int dv = tid & 31, part = tid >> 5;

    for (int i = tid; i < 128 * 32; i += 256) st[i] = 0.f;

    for (int n = 0; n < NCH; n++) {
        size_t qk_off = (((size_t)b*HKq + hq)*S_ + (size_t)n*CHUNK) * DKd;
        size_t kv_off = (((size_t)b*HVv + h )*S_ + (size_t)n*CHUNK) * DKd;
        size_t gb_off = ((size_t)b*HVv + h)*S_ + (size_t)n*CHUNK;
        __syncthreads();
        for (int i = tid; i < 64 * 128; i += 256) {
            int r = i >> 7, d = i & 127;
            q_s  [r*SP + d] = g_q  [qk_off + i];
            k_s  [r*SP + d] = g_k  [qk_off + i];
            kcd_s[r*SP + d] = g_kcd[kv_off + i];
        }
        for (int i = tid; i < 4096; i += 256) attn_s[i] = g_attn[gb_off*CHUNK + i];
        for (int i = tid; i < 2048; i += 256) {
            int c = i >> 5, d = i & 31;
            vadj_s[i] = g_vadj[kv_off + (size_t)c*128 + dvt*32 + d];
        }
        if (tid < 64) { float gv = g_gc[gb_off + tid]; gc_s[tid] = gv; eg_s[tid] = expf(gv); }
        __syncthreads();
        if (tid < 64) ek_s[tid] = expf(gc_s[63] - gc_s[tid]);

        float acc[8];
#pragma unroll
        for (int ii = 0; ii < 8; ii++) acc[ii] = vadj_s[(part + ii*8)*32 + dv];
        for (int dk = 0; dk < 128; dk++) {
            float sv = st[dk*32 + dv];
#pragma unroll
            for (int ii = 0; ii < 8; ii++) acc[ii] -= kcd_s[(part + ii*8)*SP + dk] * sv;
        }
#pragma unroll
        for (int ii = 0; ii < 8; ii++) vnew_s[(part + ii*8)*32 + dv] = acc[ii];
        __syncthreads();

        float oc[8];
#pragma unroll
        for (int ii = 0; ii < 8; ii++) oc[ii] = 0.f;
        for (int dk = 0; dk < 128; dk++) {
            float sv = st[dk*32 + dv];
#pragma unroll
            for (int ii = 0; ii < 8; ii++) oc[ii] += q_s[(part + ii*8)*SP + dk] * sv;
        }
#pragma unroll
        for (int ii = 0; ii < 8; ii++) oc[ii] *= eg_s[part + ii*8];
        for (int j = 0; j < 64; j++) {
            float vv = vnew_s[j*32 + dv];
#pragma unroll
            for (int ii = 0; ii < 8; ii++) oc[ii] += attn_s[(part + ii*8)*64 + j] * vv;
        }
        size_t o_base = ((size_t)b*S_ + (size_t)n*CHUNK) * VALUE_DIM + (size_t)h*DVd + dvt*32 + dv;
#pragma unroll
        for (int ii = 0; ii < 8; ii++)
            g_o[o_base + (size_t)(part + ii*8) * VALUE_DIM] = oc[ii];
        __syncthreads();

        float egl = eg_s[63];
        float sa[16];
#pragma unroll
        for (int ii = 0; ii < 16; ii++) sa[ii] = st[(part + ii*8)*32 + dv] * egl;
        for (int c = 0; c < 64; c++) {
            float vv = vnew_s[c*32 + dv] * ek_s[c];
#pragma unroll
            for (int ii = 0; ii < 16; ii++) sa[ii] += k_s[c*SP + (part + ii*8)] * vv;
        }
#pragma unroll
        for (int ii = 0; ii < 16; ii++) st[(part + ii*8)*32 + dv] = sa[ii];
    }
}

// -------- gated RMSNorm --------
__global__ void gated_norm(const float* __restrict__ nw) {
    int bs = blockIdx.x;
    int warp = threadIdx.x >> 5, lane = threadIdx.x & 31;
    for (int h = warp; h < HVv; h += 8) {
        size_t off = (size_t)bs * VALUE_DIM + (size_t)h * DVd;
        float4 v = ((float4*)(g_o + off))[lane];
        float ss = v.x*v.x + v.y*v.y + v.z*v.z + v.w*v.w;
#pragma unroll
        for (int o = 16; o; o >>= 1) ss += __shfl_xor_sync(~0u, ss, o);
        float r = rsqrtf(ss / 128.f + 1e-6f);
        size_t zoff = (size_t)bs * QKVZ_N + 2*KEY_DIM + VALUE_DIM + (size_t)h * DVd;
        float4 z = ((const float4*)(g_qkvz + zoff))[lane];
        float4 w = ((const float4*)nw)[lane];
        v.x = v.x * r * w.x * (z.x / (1.f + expf(-z.x)));
        v.y = v.y * r * w.y * (z.y / (1.f + expf(-z.y)));
        v.z = v.z * r * w.z * (z.z / (1.f + expf(-z.z)));
        v.w = v.w * r * w.w * (z.w / (1.f + expf(-z.w)));
        ((float4*)(g_o + off))[lane] = v;
    }
}

// ---------------- launcher ----------------
extern "C" void kernel_launch(void* const* d_in, const int* in_sizes, int n_in,
                              void* d_out, int out_size) {
    const float* hidden = (const float*)d_in[0];
    const float* Wqkvz  = (const float*)d_in[1];
    const float* Wba    = (const float*)d_in[2];
    const float* convw  = (const float*)d_in[3];
    const float* dtb    = (const float*)d_in[4];
    const float* Alog   = (const float*)d_in[5];
    const float* nw     = (const float*)d_in[6];
    const float* Wout   = (const float*)d_in[7];
    float* out = (float*)d_out;

    float *qkvz_p, *o_p;
    __nv_bfloat16 *p_p, *q_p, *r_p, *s_p;
    cudaGetSymbolAddress((void**)&qkvz_p, g_qkvz);
    cudaGetSymbolAddress((void**)&o_p, g_o);
    cudaGetSymbolAddress((void**)&p_p, g_p);
    cudaGetSymbolAddress((void**)&q_p, g_q2);
    cudaGetSymbolAddress((void**)&r_p, g_r);
    cudaGetSymbolAddress((void**)&s_p, g_s2);

    const int SMEM3 = (3*64*SP + 64*64 + 64*65) * 4;
    const int SMEM4 = (3*64*SP + 4096 + 2048 + 2048 + 128*32) * 4;
    const int SMEM_MM = 3 * STG_SZ * 2;             // 3 stages * 40960 B = 122880
    cudaFuncSetAttribute(chunk_prep, cudaFuncAttributeMaxDynamicSharedMemorySize, SMEM3);
    cudaFuncSetAttribute(scan_kernel, cudaFuncAttributeMaxDynamicSharedMemorySize, SMEM4);
    cudaFuncSetAttribute(mmgemm, cudaFuncAttributeMaxDynamicSharedMemorySize, SMEM_MM);

    // --- GEMM1: qkvz = hidden @ W_qkvz  (split bf16, HMMA) ---
    cvt_split<<<(BSz*(size_t)HID)/1024, 256>>>(hidden, p_p, q_p);
    cvt_split_T<<<dim3(QKVZ_N/32, HID/32), dim3(32,8)>>>(Wqkvz, r_p, s_p, HID, QKVZ_N);
    mmgemm<<<dim3(QKVZ_N/128, BSz/128), 256, SMEM_MM>>>(p_p, q_p, r_p, s_p, qkvz_p, BSz, QKVZ_N, HID);

    // --- small BA projection (fp32 SIMT) ---
    gemm_ba<<<BSz/16, 256>>>(hidden, Wba);

    // --- conv + gates, chunk prep, scan, norm ---
    conv_gate<<<BSz, 256>>>(convw, dtb, Alog);
    chunk_prep<<<B_*HVv*NCH, 256, SMEM3>>>();
    scan_kernel<<<dim3(B_*HVv, 4), 256, SMEM4>>>();
    gated_norm<<<BSz, 256>>>(nw);

    // --- GEMM2: out = o @ W_out (split bf16, HMMA) ---
    cvt_split<<<(BSz*(size_t)VALUE_DIM)/1024, 256>>>(o_p, r_p, s_p);
    cvt_split_T<<<dim3(HID/32, VALUE_DIM/32), dim3(32,8)>>>(Wout, p_p, q_p, VALUE_DIM, HID);
    mmgemm<<<dim3(HID/128, BSz/128), 256, SMEM_MM>>>(r_p, s_p, p_p, q_p, out, BSz, HID, VALUE_DIM);
}

// round 4
// speedup vs baseline: 2.0241x; 1.2510x over previous
#include <cuda_runtime.h>
#include <cuda_bf16.h>
#include <cuda_fp16.h>
#include <math.h>
#include <stdint.h>

// ---------------- problem constants ----------------
#define B_   2
#define S_   2048
#define HID  2048
#define HKq  16
#define HVv  32
#define DKd  128
#define DVd  128
#define KC   4
#define CHUNK 64
#define NCH  (S_/CHUNK)          // 32
#define KEY_DIM 2048
#define VALUE_DIM 4096
#define CONV_DIM 8192
#define QKVZ_N 12288
#define BSz  (B_*S_)             // 4096
#define QSCALE 0.08838834764831845f   // DK^-0.5
#define SP 129                   // padded smem row stride for 128-wide fp32 tiles

// ---------------- scratch (static device memory; no allocations) ------------
__device__ float g_qkvz[(size_t)BSz*QKVZ_N];               // [BS,12288] q|k|v|z
__device__ float g_ba[(size_t)BSz*64];
__device__ float g_q[(size_t)B_*HKq*S_*DKd];
__device__ float g_k[(size_t)B_*HKq*S_*DKd];
__device__ float g_v[(size_t)B_*HVv*S_*DVd];
__device__ float g_g[(size_t)B_*HVv*S_];
__device__ float g_beta[(size_t)B_*HVv*S_];
__device__ float g_gc[(size_t)B_*HVv*S_];
__device__ float g_vadj[(size_t)B_*HVv*S_*DVd];
__device__ float g_kcd[(size_t)B_*HVv*S_*DKd];
__device__ float g_attn[(size_t)B_*HVv*S_*CHUNK];
__device__ float g_o[(size_t)BSz*VALUE_DIM];

// fp16 operand buffers (reused across the two GEMMs)
__device__ __half g_p [(size_t)8388608];    // A1 hi  / B2t hi
__device__ __half g_q2[(size_t)8388608];    //        / B2t lo
__device__ __half g_r [(size_t)25165824];   // B1t hi / A2 hi
__device__ __half g_s2[(size_t)25165824];   // B1t lo /

__device__ __forceinline__ uint32_t smem_u32(const void* p) {
    uint32_t a;
    asm("{ .reg .u64 t; cvta.to.shared.u64 t, %1; cvt.u32.u64 %0, t; }" : "=r"(a) : "l"(p));
    return a;
}

// ---------------- fp32 -> fp16 (elementwise, float4) ----------------
__global__ void cvt_h(const float* __restrict__ X, __half* __restrict__ H) {
    size_t i = ((size_t)blockIdx.x * 256 + threadIdx.x) * 4;
    float4 v = *(const float4*)&X[i];
    __half2 h0 = __floats2half2_rn(v.x, v.y);
    __half2 h1 = __floats2half2_rn(v.z, v.w);
    uint2 hv;
    hv.x = *(uint32_t*)&h0; hv.y = *(uint32_t*)&h1;
    *(uint2*)&H[i] = hv;
}

// ---------------- fp32 [K,N] -> fp16 hi/lo [N,K] transpose split ----------------
__global__ void cvt_split_T(const float* __restrict__ W, __half* __restrict__ Ht,
                            __half* __restrict__ Lt, int K, int N) {
    __shared__ float tile[32][33];
    int n0 = blockIdx.x * 32, k0 = blockIdx.y * 32;
    int tx = threadIdx.x, ty = threadIdx.y;   // 32 x 8
#pragma unroll
    for (int j = 0; j < 32; j += 8)
        tile[ty + j][tx] = W[(size_t)(k0 + ty + j) * N + n0 + tx];
    __syncthreads();
#pragma unroll
    for (int j = 0; j < 32; j += 8) {
        float v = tile[tx][ty + j];
        __half h = __float2half_rn(v);
        __half l = __float2half_rn(v - __half2float(h));
        size_t o = (size_t)(n0 + ty + j) * K + k0 + tx;
        Ht[o] = h; Lt[o] = l;
    }
}

// ============ split-fp16 HMMA GEMM: C[M,N] = A[M,K] @ Bt[N,K]^T ============
// acc = Ah*Bh + Ah*Bl (fp32 accum); 128x128 CTA tile, BK=32, 3-stage cp.async,
// 2 CTAs/SM (92KB smem/CTA).
#define PSH 40                     // padded fp16 row stride (conflict-free ldmatrix)
#define TEN2 (128*PSH)             // elements per tensor tile (5120)
#define STG2 (3*TEN2)              // elements per stage (Ah|Bh|Bl)

__device__ __forceinline__ void mma_f16(float* c, const uint32_t* a, const uint32_t* b) {
    asm volatile("mma.sync.aligned.m16n8k16.row.col.f32.f16.f16.f32 "
                 "{%0,%1,%2,%3}, {%4,%5,%6,%7}, {%8,%9}, {%0,%1,%2,%3};"
                 : "+f"(c[0]), "+f"(c[1]), "+f"(c[2]), "+f"(c[3])
                 : "r"(a[0]), "r"(a[1]), "r"(a[2]), "r"(a[3]), "r"(b[0]), "r"(b[1]));
}
__device__ __forceinline__ void ldmx4(uint32_t* r, uint32_t addr) {
    asm volatile("ldmatrix.sync.aligned.m8n8.x4.shared.b16 {%0,%1,%2,%3}, [%4];"
                 : "=r"(r[0]), "=r"(r[1]), "=r"(r[2]), "=r"(r[3]) : "r"(addr));
}

__device__ __forceinline__ void stage_load(uint32_t sbase_b, int stage,
    const __half* a0, const __half* b0, const __half* b1,
    int K, int kt, int tid)
{
    const __half* gp[3] = {a0, b0, b1};
    uint32_t st_b = sbase_b + (uint32_t)stage * (STG2 * 2);
#pragma unroll
    for (int t = 0; t < 3; t++) {
        uint32_t tb = st_b + (uint32_t)t * (TEN2 * 2);
#pragma unroll
        for (int j = 0; j < 2; j++) {
            int idx = j * 256 + tid;
            int row = idx >> 2, c16 = idx & 3;
            uint32_t sa = tb + (uint32_t)(row * (PSH*2) + c16 * 16);
            const void* ga = gp[t] + (size_t)row * K + (size_t)kt * 32 + c16 * 8;
            asm volatile("cp.async.cg.shared.global [%0], [%1], 16;" :: "r"(sa), "l"(ga));
        }
    }
    asm volatile("cp.async.commit_group;" ::: "memory");
}

__global__ void __launch_bounds__(256, 2) mmgemm(
    const __half* __restrict__ Ah,
    const __half* __restrict__ Bh, const __half* __restrict__ Bl,
    float* __restrict__ C, int M, int N, int K)
{
    extern __shared__ __half smem[];
    uint32_t sbase = smem_u32(smem);
    int tid = threadIdx.x, lane = tid & 31, wid = tid >> 5;
    int warpM = wid >> 2, warpN = wid & 3;      // 2 x 4 warp grid
    int bn = blockIdx.x, bm = blockIdx.y;
    const int T = K >> 5;

    const __half* a0 = Ah + (size_t)bm * 128 * K;
    const __half* b0 = Bh + (size_t)bn * 128 * K;
    const __half* b1 = Bl + (size_t)bn * 128 * K;

    // ldmatrix per-lane element offsets (in fp16 elements)
    int g = lane >> 3, lr = lane & 7;
    uint32_t aoff = (uint32_t)((warpM*64 + (g&1)*8 + lr) * PSH + (g>>1)*8);
    uint32_t boff = (uint32_t)((warpN*32 + (g>>1)*8 + lr) * PSH + (g&1)*8);

    float acc[4][4][4];
#pragma unroll
    for (int i = 0; i < 4; i++)
#pragma unroll
        for (int j = 0; j < 4; j++)
#pragma unroll
            for (int r = 0; r < 4; r++) acc[i][j][r] = 0.f;

    stage_load(sbase, 0, a0, b0, b1, K, 0, tid);
    stage_load(sbase, 1, a0, b0, b1, K, 1, tid);

    for (int kt = 0; kt < T; kt++) {
        if (kt + 1 < T) asm volatile("cp.async.wait_group 1;" ::: "memory");
        else            asm volatile("cp.async.wait_group 0;" ::: "memory");
        __syncthreads();
        if (kt + 2 < T) stage_load(sbase, (kt + 2) % 3, a0, b0, b1, K, kt + 2, tid);

        uint32_t st = sbase + (uint32_t)(kt % 3) * (STG2 * 2);
        uint32_t sAh = st, sBh = st + TEN2*2, sBl = st + 2*TEN2*2;
#pragma unroll
        for (int ks = 0; ks < 2; ks++) {
            int kk = ks * 16;
            uint32_t ah[4][4], bh[4][2], bl[4][2];
#pragma unroll
            for (int mi = 0; mi < 4; mi++)
                ldmx4(ah[mi], sAh + (aoff + mi*16*PSH + kk) * 2);
#pragma unroll
            for (int p = 0; p < 2; p++) {
                uint32_t off = (boff + p*16*PSH + kk) * 2;
                uint32_t rh[4], rl[4];
                ldmx4(rh, sBh + off);
                ldmx4(rl, sBl + off);
                bh[2*p][0] = rh[0]; bh[2*p][1] = rh[1];
                bh[2*p+1][0] = rh[2]; bh[2*p+1][1] = rh[3];
                bl[2*p][0] = rl[0]; bl[2*p][1] = rl[1];
                bl[2*p+1][0] = rl[2]; bl[2*p+1][1] = rl[3];
            }
#pragma unroll
            for (int mi = 0; mi < 4; mi++)
#pragma unroll
                for (int ni = 0; ni < 4; ni++) {
                    mma_f16(acc[mi][ni], ah[mi], bh[ni]);
                    mma_f16(acc[mi][ni], ah[mi], bl[ni]);
                }
        }
        __syncthreads();
    }

    // epilogue: fragment -> C
    int rr = lane >> 2, cc = (lane & 3) * 2;
#pragma unroll
    for (int mi = 0; mi < 4; mi++) {
        int row0 = bm * 128 + warpM * 64 + mi * 16 + rr;
#pragma unroll
        for (int ni = 0; ni < 4; ni++) {
            int col = bn * 128 + warpN * 32 + ni * 8 + cc;
            float2 v0 = make_float2(acc[mi][ni][0], acc[mi][ni][1]);
            float2 v1 = make_float2(acc[mi][ni][2], acc[mi][ni][3]);
            *(float2*)&C[(size_t)row0 * N + col]       = v0;
            *(float2*)&C[(size_t)(row0 + 8) * N + col] = v1;
        }
    }
}

// ---------------- BA projection: [BS,2048]@[2048,64], smem-staged ----------------
__global__ void gemm_ba(const float* __restrict__ X, const float* __restrict__ W) {
    __shared__ float Xs[32][65];
    __shared__ float Ws[64][64];
    int tid = threadIdx.x;
    int row0 = blockIdx.x * 32;
    int col = (tid & 15) * 4;          // 4 cols per thread
    int rg = tid >> 4;                 // 0..15 -> rows rg*2, rg*2+1
    float acc[2][4] = {};
    for (int k0 = 0; k0 < HID; k0 += 64) {
        // load X tile 32x64 (coalesced over k)
#pragma unroll
        for (int j = 0; j < 8; j++) {
            int idx = j * 256 + tid;
            int r = idx >> 6, kk = idx & 63;
            Xs[r][kk] = X[(size_t)(row0 + r) * HID + k0 + kk];
        }
        // load W tile 64x64
#pragma unroll
        for (int j = 0; j < 16; j++) {
            int idx = j * 256 + tid;
            int kk = idx >> 6, c = idx & 63;
            Ws[kk][c] = W[(size_t)(k0 + kk) * 64 + c];
        }
        __syncthreads();
#pragma unroll 8
        for (int kk = 0; kk < 64; kk++) {
            float a0 = Xs[rg*2][kk], a1 = Xs[rg*2+1][kk];
            float4 b = *(float4*)&Ws[kk][col];
            acc[0][0] += a0*b.x; acc[0][1] += a0*b.y; acc[0][2] += a0*b.z; acc[0][3] += a0*b.w;
            acc[1][0] += a1*b.x; acc[1][1] += a1*b.y; acc[1][2] += a1*b.z; acc[1][3] += a1*b.w;
        }
        __syncthreads();
    }
#pragma unroll
    for (int r = 0; r < 2; r++)
        *(float4*)&g_ba[(size_t)(row0 + rg*2 + r) * 64 + col] =
            make_float4(acc[r][0], acc[r][1], acc[r][2], acc[r][3]);
}

// -------- conv + silu + l2norm + head transpose + gates --------
__global__ void conv_gate(const float* __restrict__ cw, const float* __restrict__ dtb,
                          const float* __restrict__ Alog) {
    int bs = blockIdx.x;
    int b = bs / S_, s = bs % S_;
    int tid = threadIdx.x;
    __shared__ float cs[CONV_DIM];
    __shared__ float hsum[32];
    const float* base = g_qkvz + (size_t)bs * QKVZ_N;

    for (int c = tid; c < CONV_DIM; c += 256) {
        float w0 = cw[c*4+0], w1 = cw[c*4+1], w2 = cw[c*4+2], w3 = cw[c*4+3];
        float acc = base[c] * w3;
        if (s >= 1) acc += base[c - (size_t)QKVZ_N] * w2;
        if (s >= 2) acc += base[c - (size_t)2*QKVZ_N] * w1;
        if (s >= 3) acc += base[c - (size_t)3*QKVZ_N] * w0;
        cs[c] = acc / (1.f + __expf(-acc));
    }
    __syncthreads();
    int warp = tid >> 5, lane = tid & 31;
    for (int h = warp; h < 32; h += 8) {
        float ss = 0.f;
        for (int d = lane; d < 128; d += 32) { float v = cs[h*128 + d]; ss += v * v; }
#pragma unroll
        for (int o = 16; o; o >>= 1) ss += __shfl_xor_sync(~0u, ss, o);
        if (!lane) hsum[h] = rsqrtf(ss + 1e-6f);
    }
    __syncthreads();
    for (int c = tid; c < KEY_DIM; c += 256) {
        int h = c >> 7, d = c & 127;
        g_q[(((size_t)b*HKq + h)*S_ + s)*DKd + d] = cs[c] * hsum[h] * QSCALE;
    }
    for (int c = tid; c < KEY_DIM; c += 256) {
        int h = c >> 7, d = c & 127;
        g_k[(((size_t)b*HKq + h)*S_ + s)*DKd + d] = cs[KEY_DIM + c] * hsum[16 + h];
    }
    for (int c = tid; c < VALUE_DIM; c += 256) {
        int h = c >> 7, d = c & 127;
        g_v[(((size_t)b*HVv + h)*S_ + s)*DVd + d] = cs[2*KEY_DIM + c];
    }
    if (tid < 32) {
        float bb = g_ba[(size_t)bs*64 + tid];
        g_beta[((size_t)b*HVv + tid)*S_ + s] = 1.f / (1.f + expf(-bb));
    } else if (tid < 64) {
        int h = tid - 32;
        float a = g_ba[(size_t)bs*64 + 32 + h] + dtb[h];
        float sp = (a > 20.f) ? a : log1pf(expf(a));
        g_g[((size_t)b*HVv + h)*S_ + s] = -expf(Alog[h]) * sp;
    }
}

__device__ __forceinline__ float dot128(const float* a, const float* b) {
    float s0 = 0.f, s1 = 0.f, s2 = 0.f, s3 = 0.f;
#pragma unroll
    for (int d = 0; d < 128; d += 4) {
        s0 += a[d]   * b[d];
        s1 += a[d+1] * b[d+1];
        s2 += a[d+2] * b[d+2];
        s3 += a[d+3] * b[d+3];
    }
    return (s0 + s1) + (s2 + s3);
}

// -------- per-(b,h,chunk) intra-chunk quantities --------
__global__ void chunk_prep() {
    extern __shared__ float sm[];
    float* q_s  = sm;
    float* k_s  = q_s  + 64*SP;
    float* vb_s = k_s  + 64*SP;
    float* A_s  = vb_s + 64*SP;
    float* T_s  = A_s  + 64*64;
    __shared__ float gc_s[64], beta_s[64], kbe_s[64];

    int blk = blockIdx.x;
    int n = blk & 31, h = (blk >> 5) & 31, b = blk >> 10;
    int hq = h >> 1;
    int tid = threadIdx.x;

    size_t qk_off = (((size_t)b*HKq + hq)*S_ + (size_t)n*CHUNK) * DKd;
    size_t v_off  = (((size_t)b*HVv + h )*S_ + (size_t)n*CHUNK) * DVd;
    size_t gb_off = ((size_t)b*HVv + h)*S_ + (size_t)n*CHUNK;

    if (tid < 64) { gc_s[tid] = g_g[gb_off + tid]; beta_s[tid] = g_beta[gb_off + tid]; }
    __syncthreads();
    if (tid == 0) { for (int i = 1; i < 64; i++) gc_s[i] += gc_s[i - 1]; }
    __syncthreads();
    if (tid < 64) {
        g_gc[gb_off + tid] = gc_s[tid];
        kbe_s[tid] = beta_s[tid] * expf(gc_s[tid]);
    }
    for (int i = tid; i < 64 * 128; i += 256) {
        int r = i >> 7, d = i & 127;
        q_s [r*SP + d] = g_q[qk_off + i];
        k_s [r*SP + d] = g_k[qk_off + i];
        vb_s[r*SP + d] = g_v[v_off + i] * beta_s[r];
    }
    __syncthreads();

    for (int i = tid; i < 4096; i += 256) {
        int c = i >> 6, j = i & 63;
        float val = 0.f;
        if (j < c)
            val = dot128(&k_s[c*SP], &k_s[j*SP]) * beta_s[c] * expf(gc_s[c] - gc_s[j]);
        A_s[i] = val;
    }
    __syncthreads();

    if (tid < 64) {
        int col = tid;
        for (int c = 0; c < 64; c++) {
            float ssum = (c == col) ? 1.f : 0.f;
            for (int j = col; j < c; j++) ssum -= A_s[c*64 + j] * T_s[j*65 + col];
            T_s[c*65 + col] = (c >= col) ? ssum : 0.f;
        }
    }
    __syncthreads();

    size_t kcd_off = (((size_t)b*HVv + h)*S_ + (size_t)n*CHUNK) * DKd;
    for (int i = tid; i < 64 * 128; i += 256) {
        int c = i >> 7, d = i & 127;
        float av = 0.f, ak = 0.f;
#pragma unroll 4
        for (int j = 0; j <= c; j++) {
            float t = T_s[c*65 + j];
            av += t * vb_s[j*SP + d];
            ak += t * k_s[j*SP + d] * kbe_s[j];
        }
        g_vadj[v_off + i]  = av;
        g_kcd [kcd_off + i] = ak;
    }
    size_t at_off = gb_off * CHUNK;
    for (int i = tid; i < 4096; i += 256) {
        int c = i >> 6, j = i & 63;
        float val = 0.f;
        if (j <= c)
            val = dot128(&q_s[c*SP], &k_s[j*SP]) * expf(gc_s[c] - gc_s[j]);
        g_attn[at_off + i] = val;
    }
}

// -------- sequential scan over chunks --------
__global__ void scan_kernel() {
    extern __shared__ float sm[];
    float* q_s    = sm;
    float* k_s    = q_s   + 64*SP;
    float* kcd_s  = k_s   + 64*SP;
    float* attn_s = kcd_s + 64*SP;
    float* vadj_s = attn_s + 4096;
    float* vnew_s = vadj_s + 2048;
    float* st     = vnew_s + 2048;
    __shared__ float gc_s[64], eg_s[64], ek_s[64];

    int bh = blockIdx.x, dvt = blockIdx.y;
    int b = bh >> 5, h = bh & 31, hq = h >> 1;
    int tid = threadIdx.x;
    int dv = tid & 31, part = tid >> 5;

    for (int i = tid; i < 128 * 32; i += 256) st[i] = 0.f;

    for (int n = 0; n < NCH; n++) {
        size_t qk_off = (((size_t)b*HKq + hq)*S_ + (size_t)n*CHUNK) * DKd;
        size_t kv_off = (((size_t)b*HVv + h )*S_ + (size_t)n*CHUNK) * DKd;
        size_t gb_off = ((size_t)b*HVv + h)*S_ + (size_t)n*CHUNK;
        __syncthreads();
        for (int i = tid; i < 64 * 128; i += 256) {
            int r = i >> 7, d = i & 127;
            q_s  [r*SP + d] = g_q  [qk_off + i];
            k_s  [r*SP + d] = g_k  [qk_off + i];
            kcd_s[r*SP + d] = g_kcd[kv_off + i];
        }
        for (int i = tid; i < 4096; i += 256) attn_s[i] = g_attn[gb_off*CHUNK + i];
        for (int i = tid; i < 2048; i += 256) {
            int c = i >> 5, d = i & 31;
            vadj_s[i] = g_vadj[kv_off + (size_t)c*128 + dvt*32 + d];
        }
        if (tid < 64) { float gv = g_gc[gb_off + tid]; gc_s[tid] = gv; eg_s[tid] = expf(gv); }
        __syncthreads();
        if (tid < 64) ek_s[tid] = expf(gc_s[63] - gc_s[tid]);

        float acc[8];
#pragma unroll
        for (int ii = 0; ii < 8; ii++) acc[ii] = vadj_s[(part + ii*8)*32 + dv];
        for (int dk = 0; dk < 128; dk++) {
            float sv = st[dk*32 + dv];
#pragma unroll
            for (int ii = 0; ii < 8; ii++) acc[ii] -= kcd_s[(part + ii*8)*SP + dk] * sv;
        }
#pragma unroll
        for (int ii = 0; ii < 8; ii++) vnew_s[(part + ii*8)*32 + dv] = acc[ii];
        __syncthreads();

        float oc[8];
#pragma unroll
        for (int ii = 0; ii < 8; ii++) oc[ii] = 0.f;
        for (int dk = 0; dk < 128; dk++) {
            float sv = st[dk*32 + dv];
#pragma unroll
            for (int ii = 0; ii < 8; ii++) oc[ii] += q_s[(part + ii*8)*SP + dk] * sv;
        }
#pragma unroll
        for (int ii = 0; ii < 8; ii++) oc[ii] *= eg_s[part + ii*8];
        for (int j = 0; j < 64; j++) {
            float vv = vnew_s[j*32 + dv];
#pragma unroll
            for (int ii = 0; ii < 8; ii++) oc[ii] += attn_s[(part + ii*8)*64 + j] * vv;
        }
        size_t o_base = ((size_t)b*S_ + (size_t)n*CHUNK) * VALUE_DIM + (size_t)h*DVd + dvt*32 + dv;
#pragma unroll
        for (int ii = 0; ii < 8; ii++)
            g_o[o_base + (size_t)(part + ii*8) * VALUE_DIM] = oc[ii];
        __syncthreads();

        float egl = eg_s[63];
        float sa[16];
#pragma unroll
        for (int ii = 0; ii < 16; ii++) sa[ii] = st[(part + ii*8)*32 + dv] * egl;
        for (int c = 0; c < 64; c++) {
            float vv = vnew_s[c*32 + dv] * ek_s[c];
#pragma unroll
            for (int ii = 0; ii < 16; ii++) sa[ii] += k_s[c*SP + (part + ii*8)] * vv;
        }
#pragma unroll
        for (int ii = 0; ii < 16; ii++) st[(part + ii*8)*32 + dv] = sa[ii];
    }
}

// -------- gated RMSNorm --------
__global__ void gated_norm(const float* __restrict__ nw) {
    int bs = blockIdx.x;
    int warp = threadIdx.x >> 5, lane = threadIdx.x & 31;
    for (int h = warp; h < HVv; h += 8) {
        size_t off = (size_t)bs * VALUE_DIM + (size_t)h * DVd;
        float4 v = ((float4*)(g_o + off))[lane];
        float ss = v.x*v.x + v.y*v.y + v.z*v.z + v.w*v.w;
#pragma unroll
        for (int o = 16; o; o >>= 1) ss += __shfl_xor_sync(~0u, ss, o);
        float r = rsqrtf(ss / 128.f + 1e-6f);
        size_t zoff = (size_t)bs * QKVZ_N + 2*KEY_DIM + VALUE_DIM + (size_t)h * DVd;
        float4 z = ((const float4*)(g_qkvz + zoff))[lane];
        float4 w = ((const float4*)nw)[lane];
        v.x = v.x * r * w.x * (z.x / (1.f + expf(-z.x)));
        v.y = v.y * r * w.y * (z.y / (1.f + expf(-z.y)));
        v.z = v.z * r * w.z * (z.z / (1.f + expf(-z.z)));
        v.w = v.w * r * w.w * (z.w / (1.f + expf(-z.w)));
        ((float4*)(g_o + off))[lane] = v;
    }
}

// ---------------- launcher ----------------
extern "C" void kernel_launch(void* const* d_in, const int* in_sizes, int n_in,
                              void* d_out, int out_size) {
    const float* hidden = (const float*)d_in[0];
    const float* Wqkvz  = (const float*)d_in[1];
    const float* Wba    = (const float*)d_in[2];
    const float* convw  = (const float*)d_in[3];
    const float* dtb    = (const float*)d_in[4];
    const float* Alog   = (const float*)d_in[5];
    const float* nw     = (const float*)d_in[6];
    const float* Wout   = (const float*)d_in[7];
    float* out = (float*)d_out;

    float *qkvz_p, *o_p;
    __half *p_p, *q_p, *r_p, *s_p;
    cudaGetSymbolAddress((void**)&qkvz_p, g_qkvz);
    cudaGetSymbolAddress((void**)&o_p, g_o);
    cudaGetSymbolAddress((void**)&p_p, g_p);
    cudaGetSymbolAddress((void**)&q_p, g_q2);
    cudaGetSymbolAddress((void**)&r_p, g_r);
    cudaGetSymbolAddress((void**)&s_p, g_s2);

    const int SMEM3 = (3*64*SP + 64*64 + 64*65) * 4;
    const int SMEM4 = (3*64*SP + 4096 + 2048 + 2048 + 128*32) * 4;
    const int SMEM_MM = 3 * STG2 * 2;               // 3 stages * 30720 B = 92160
    cudaFuncSetAttribute(chunk_prep, cudaFuncAttributeMaxDynamicSharedMemorySize, SMEM3);
    cudaFuncSetAttribute(scan_kernel, cudaFuncAttributeMaxDynamicSharedMemorySize, SMEM4);
    cudaFuncSetAttribute(mmgemm, cudaFuncAttributeMaxDynamicSharedMemorySize, SMEM_MM);

    // --- GEMM1: qkvz = hidden @ W_qkvz  (split fp16, HMMA) ---
    cvt_h<<<(BSz*(size_t)HID)/1024, 256>>>(hidden, p_p);
    cvt_split_T<<<dim3(QKVZ_N/32, HID/32), dim3(32,8)>>>(Wqkvz, r_p, s_p, HID, QKVZ_N);
    mmgemm<<<dim3(QKVZ_N/128, BSz/128), 256, SMEM_MM>>>(p_p, r_p, s_p, qkvz_p, BSz, QKVZ_N, HID);

    // --- small BA projection (fp32 SIMT, smem-staged) ---
    gemm_ba<<<BSz/32, 256>>>(hidden, Wba);

    // --- conv + gates, chunk prep, scan, norm ---
    conv_gate<<<BSz, 256>>>(convw, dtb, Alog);
    chunk_prep<<<B_*HVv*NCH, 256, SMEM3>>>();
    scan_kernel<<<dim3(B_*HVv, 4), 256, SMEM4>>>();
    gated_norm<<<BSz, 256>>>(nw);

    // --- GEMM2: out = o @ W_out (split fp16, HMMA) ---
    cvt_h<<<(BSz*(size_t)VALUE_DIM)/1024, 256>>>(o_p, r_p);
    cvt_split_T<<<dim3(HID/32, VALUE_DIM/32), dim3(32,8)>>>(Wout, p_p, q_p, VALUE_DIM, HID);
    mmgemm<<<dim3(HID/128, BSz/128), 256, SMEM_MM>>>(r_p, p_p, q_p, out, BSz, HID, VALUE_DIM);
}

// round 5
// speedup vs baseline: 2.0767x; 1.0260x over previous
#include <cuda_runtime.h>
#include <cuda_bf16.h>
#include <cuda_fp16.h>
#include <math.h>
#include <stdint.h>

// ---------------- problem constants ----------------
#define B_   2
#define S_   2048
#define HID  2048
#define HKq  16
#define HVv  32
#define DKd  128
#define DVd  128
#define KC   4
#define CHUNK 64
#define NCH  (S_/CHUNK)          // 32
#define KEY_DIM 2048
#define VALUE_DIM 4096
#define CONV_DIM 8192
#define QKVZ_N 12288
#define BSz  (B_*S_)             // 4096
#define QSCALE 0.08838834764831845f   // DK^-0.5
#define SP 129                   // padded smem row stride for 128-wide fp32 tiles

// ---------------- scratch (static device memory; no allocations) ------------
__device__ float g_qkvz[(size_t)BSz*QKVZ_N];               // [BS,12288] q|k|v|z
__device__ float g_ba[(size_t)BSz*64];
__device__ float g_bap[(size_t)8*BSz*64];                  // split-K partials
__device__ float g_q[(size_t)B_*HKq*S_*DKd];
__device__ float g_k[(size_t)B_*HKq*S_*DKd];
__device__ float g_v[(size_t)B_*HVv*S_*DVd];
__device__ float g_g[(size_t)B_*HVv*S_];
__device__ float g_beta[(size_t)B_*HVv*S_];
__device__ float g_gc[(size_t)B_*HVv*S_];
__device__ float g_vadj[(size_t)B_*HVv*S_*DVd];
__device__ float g_kcd[(size_t)B_*HVv*S_*DKd];
__device__ float g_attn[(size_t)B_*HVv*S_*CHUNK];
__device__ float g_o[(size_t)BSz*VALUE_DIM];

// fp16 operand buffers (reused across the two GEMMs)
__device__ __half g_p [(size_t)8388608];    // A1     / B2t hi
__device__ __half g_q2[(size_t)8388608];    //        / B2t lo
__device__ __half g_r [(size_t)25165824];   // B1t hi / A2
__device__ __half g_s2[(size_t)25165824];   // B1t lo /

__device__ __forceinline__ uint32_t smem_u32(const void* p) {
    uint32_t a;
    asm("{ .reg .u64 t; cvta.to.shared.u64 t, %1; cvt.u32.u64 %0, t; }" : "=r"(a) : "l"(p));
    return a;
}

// ---------------- fp32 -> fp16 (elementwise, float4) ----------------
__global__ void cvt_h(const float* __restrict__ X, __half* __restrict__ H) {
    size_t i = ((size_t)blockIdx.x * 256 + threadIdx.x) * 4;
    float4 v = *(const float4*)&X[i];
    __half2 h0 = __floats2half2_rn(v.x, v.y);
    __half2 h1 = __floats2half2_rn(v.z, v.w);
    uint2 hv;
    hv.x = *(uint32_t*)&h0; hv.y = *(uint32_t*)&h1;
    *(uint2*)&H[i] = hv;
}

// ---------------- fp32 [K,N] -> fp16 hi/lo [N,K] transpose split ----------------
__global__ void cvt_split_T(const float* __restrict__ W, __half* __restrict__ Ht,
                            __half* __restrict__ Lt, int K, int N) {
    __shared__ float tile[32][33];
    int n0 = blockIdx.x * 32, k0 = blockIdx.y * 32;
    int tx = threadIdx.x, ty = threadIdx.y;   // 32 x 8
#pragma unroll
    for (int j = 0; j < 32; j += 8)
        tile[ty + j][tx] = W[(size_t)(k0 + ty + j) * N + n0 + tx];
    __syncthreads();
#pragma unroll
    for (int j = 0; j < 32; j += 8) {
        float v = tile[tx][ty + j];
        __half h = __float2half_rn(v);
        __half l = __float2half_rn(v - __half2float(h));
        size_t o = (size_t)(n0 + ty + j) * K + k0 + tx;
        Ht[o] = h; Lt[o] = l;
    }
}

// ============ split-fp16 HMMA GEMM: C[M,N] = A[M,K] @ Bt[N,K]^T ============
// acc = Ah*Bh + Ah*Bl (fp32 accum); 128x128 CTA tile, BK=32, 3-stage cp.async,
// 2 CTAs/SM. Grid: blockIdx.x = bm (fast -> shares B panel), blockIdx.y = bn.
#define PSH 40                     // padded fp16 row stride (conflict-free ldmatrix)
#define TEN2 (128*PSH)             // elements per tensor tile (5120)
#define STG2 (3*TEN2)              // elements per stage (Ah|Bh|Bl)

__device__ __forceinline__ void mma_f16(float* c, const uint32_t* a, const uint32_t* b) {
    asm volatile("mma.sync.aligned.m16n8k16.row.col.f32.f16.f16.f32 "
                 "{%0,%1,%2,%3}, {%4,%5,%6,%7}, {%8,%9}, {%0,%1,%2,%3};"
                 : "+f"(c[0]), "+f"(c[1]), "+f"(c[2]), "+f"(c[3])
                 : "r"(a[0]), "r"(a[1]), "r"(a[2]), "r"(a[3]), "r"(b[0]), "r"(b[1]));
}
__device__ __forceinline__ void ldmx4(uint32_t* r, uint32_t addr) {
    asm volatile("ldmatrix.sync.aligned.m8n8.x4.shared.b16 {%0,%1,%2,%3}, [%4];"
                 : "=r"(r[0]), "=r"(r[1]), "=r"(r[2]), "=r"(r[3]) : "r"(addr));
}

__device__ __forceinline__ void stage_load(uint32_t sbase_b, int stage,
    const __half* a0, const __half* b0, const __half* b1,
    int K, int kt, int tid)
{
    const __half* gp[3] = {a0, b0, b1};
    uint32_t st_b = sbase_b + (uint32_t)stage * (STG2 * 2);
#pragma unroll
    for (int t = 0; t < 3; t++) {
        uint32_t tb = st_b + (uint32_t)t * (TEN2 * 2);
#pragma unroll
        for (int j = 0; j < 2; j++) {
            int idx = j * 256 + tid;
            int row = idx >> 2, c16 = idx & 3;
            uint32_t sa = tb + (uint32_t)(row * (PSH*2) + c16 * 16);
            const void* ga = gp[t] + (size_t)row * K + (size_t)kt * 32 + c16 * 8;
            asm volatile("cp.async.cg.shared.global [%0], [%1], 16;" :: "r"(sa), "l"(ga));
        }
    }
    asm volatile("cp.async.commit_group;" ::: "memory");
}

__global__ void __launch_bounds__(256, 2) mmgemm(
    const __half* __restrict__ Ah,
    const __half* __restrict__ Bh, const __half* __restrict__ Bl,
    float* __restrict__ C, int M, int N, int K)
{
    extern __shared__ __half smem[];
    uint32_t sbase = smem_u32(smem);
    int tid = threadIdx.x, lane = tid & 31, wid = tid >> 5;
    int warpM = wid >> 2, warpN = wid & 3;      // 2 x 4 warp grid
    int bm = blockIdx.x, bn = blockIdx.y;       // bm fast: consecutive CTAs share B panel
    const int T = K >> 5;

    const __half* a0 = Ah + (size_t)bm * 128 * K;
    const __half* b0 = Bh + (size_t)bn * 128 * K;
    const __half* b1 = Bl + (size_t)bn * 128 * K;

    // ldmatrix per-lane element offsets (in fp16 elements)
    int g = lane >> 3, lr = lane & 7;
    uint32_t aoff = (uint32_t)((warpM*64 + (g&1)*8 + lr) * PSH + (g>>1)*8);
    uint32_t boff = (uint32_t)((warpN*32 + (g>>1)*8 + lr) * PSH + (g&1)*8);

    float acc[4][4][4];
#pragma unroll
    for (int i = 0; i < 4; i++)
#pragma unroll
        for (int j = 0; j < 4; j++)
#pragma unroll
            for (int r = 0; r < 4; r++) acc[i][j][r] = 0.f;

    stage_load(sbase, 0, a0, b0, b1, K, 0, tid);
    stage_load(sbase, 1, a0, b0, b1, K, 1, tid);

    for (int kt = 0; kt < T; kt++) {
        if (kt + 1 < T) asm volatile("cp.async.wait_group 1;" ::: "memory");
        else            asm volatile("cp.async.wait_group 0;" ::: "memory");
        __syncthreads();
        if (kt + 2 < T) stage_load(sbase, (kt + 2) % 3, a0, b0, b1, K, kt + 2, tid);

        uint32_t st = sbase + (uint32_t)(kt % 3) * (STG2 * 2);
        uint32_t sAh = st, sBh = st + TEN2*2, sBl = st + 2*TEN2*2;
#pragma unroll
        for (int ks = 0; ks < 2; ks++) {
            int kk = ks * 16;
            uint32_t ah[4][4], bh[4][2], bl[4][2];
#pragma unroll
            for (int mi = 0; mi < 4; mi++)
                ldmx4(ah[mi], sAh + (aoff + mi*16*PSH + kk) * 2);
#pragma unroll
            for (int p = 0; p < 2; p++) {
                uint32_t off = (boff + p*16*PSH + kk) * 2;
                uint32_t rh[4], rl[4];
                ldmx4(rh, sBh + off);
                ldmx4(rl, sBl + off);
                bh[2*p][0] = rh[0]; bh[2*p][1] = rh[1];
                bh[2*p+1][0] = rh[2]; bh[2*p+1][1] = rh[3];
                bl[2*p][0] = rl[0]; bl[2*p][1] = rl[1];
                bl[2*p+1][0] = rl[2]; bl[2*p+1][1] = rl[3];
            }
#pragma unroll
            for (int mi = 0; mi < 4; mi++)
#pragma unroll
                for (int ni = 0; ni < 4; ni++) {
                    mma_f16(acc[mi][ni], ah[mi], bh[ni]);
                    mma_f16(acc[mi][ni], ah[mi], bl[ni]);
                }
        }
        __syncthreads();
    }

    // epilogue: fragment -> C
    int rr = lane >> 2, cc = (lane & 3) * 2;
#pragma unroll
    for (int mi = 0; mi < 4; mi++) {
        int row0 = bm * 128 + warpM * 64 + mi * 16 + rr;
#pragma unroll
        for (int ni = 0; ni < 4; ni++) {
            int col = bn * 128 + warpN * 32 + ni * 8 + cc;
            float2 v0 = make_float2(acc[mi][ni][0], acc[mi][ni][1]);
            float2 v1 = make_float2(acc[mi][ni][2], acc[mi][ni][3]);
            *(float2*)&C[(size_t)row0 * N + col]       = v0;
            *(float2*)&C[(size_t)(row0 + 8) * N + col] = v1;
        }
    }
}

// ------------- BA projection split-K: [BS,2048]@[2048,64] -> partials -------------
__global__ void gemm_ba_part(const float* __restrict__ X, const float* __restrict__ W) {
    __shared__ float Xs[64][65];
    __shared__ float Ws[64][64];
    int tid = threadIdx.x;
    int row0 = blockIdx.x * 64;
    int kbase = blockIdx.y * 256;
    int col = (tid & 15) * 4;
    int r0 = (tid >> 4) * 4;
    float acc[4][4] = {};
    for (int k0 = kbase; k0 < kbase + 256; k0 += 64) {
#pragma unroll
        for (int j = 0; j < 16; j++) {
            int idx = j * 256 + tid;
            int r = idx >> 6, kk = idx & 63;
            Xs[r][kk] = X[(size_t)(row0 + r) * HID + k0 + kk];
        }
#pragma unroll
        for (int j = 0; j < 16; j++) {
            int idx = j * 256 + tid;
            int kk = idx >> 6, c = idx & 63;
            Ws[kk][c] = W[(size_t)(k0 + kk) * 64 + c];
        }
        __syncthreads();
#pragma unroll 8
        for (int kk = 0; kk < 64; kk++) {
            float4 b = *(float4*)&Ws[kk][col];
#pragma unroll
            for (int r = 0; r < 4; r++) {
                float a = Xs[r0 + r][kk];
                acc[r][0] += a*b.x; acc[r][1] += a*b.y; acc[r][2] += a*b.z; acc[r][3] += a*b.w;
            }
        }
        __syncthreads();
    }
    float* dst = g_bap + (size_t)blockIdx.y * BSz * 64;
#pragma unroll
    for (int r = 0; r < 4; r++)
        *(float4*)&dst[(size_t)(row0 + r0 + r) * 64 + col] =
            make_float4(acc[r][0], acc[r][1], acc[r][2], acc[r][3]);
}
__global__ void gemm_ba_reduce() {
    size_t i = (size_t)blockIdx.x * 256 + threadIdx.x;   // over BSz*64
    float s = 0.f;
#pragma unroll
    for (int p = 0; p < 8; p++) s += g_bap[(size_t)p * BSz * 64 + i];
    g_ba[i] = s;
}

// -------- conv + silu + l2norm + head transpose + gates --------
__global__ void conv_gate(const float* __restrict__ cw, const float* __restrict__ dtb,
                          const float* __restrict__ Alog) {
    int bs = blockIdx.x;
    int b = bs / S_, s = bs % S_;
    int tid = threadIdx.x;
    __shared__ float cs[CONV_DIM];
    __shared__ float hsum[32];
    const float* base = g_qkvz + (size_t)bs * QKVZ_N;

    for (int c = tid; c < CONV_DIM; c += 256) {
        float w0 = cw[c*4+0], w1 = cw[c*4+1], w2 = cw[c*4+2], w3 = cw[c*4+3];
        float acc = base[c] * w3;
        if (s >= 1) acc += base[c - (size_t)QKVZ_N] * w2;
        if (s >= 2) acc += base[c - (size_t)2*QKVZ_N] * w1;
        if (s >= 3) acc += base[c - (size_t)3*QKVZ_N] * w0;
        cs[c] = acc / (1.f + __expf(-acc));
    }
    __syncthreads();
    int warp = tid >> 5, lane = tid & 31;
    for (int h = warp; h < 32; h += 8) {
        float ss = 0.f;
        for (int d = lane; d < 128; d += 32) { float v = cs[h*128 + d]; ss += v * v; }
#pragma unroll
        for (int o = 16; o; o >>= 1) ss += __shfl_xor_sync(~0u, ss, o);
        if (!lane) hsum[h] = rsqrtf(ss + 1e-6f);
    }
    __syncthreads();
    for (int c = tid; c < KEY_DIM; c += 256) {
        int h = c >> 7, d = c & 127;
        g_q[(((size_t)b*HKq + h)*S_ + s)*DKd + d] = cs[c] * hsum[h] * QSCALE;
    }
    for (int c = tid; c < KEY_DIM; c += 256) {
        int h = c >> 7, d = c & 127;
        g_k[(((size_t)b*HKq + h)*S_ + s)*DKd + d] = cs[KEY_DIM + c] * hsum[16 + h];
    }
    for (int c = tid; c < VALUE_DIM; c += 256) {
        int h = c >> 7, d = c & 127;
        g_v[(((size_t)b*HVv + h)*S_ + s)*DVd + d] = cs[2*KEY_DIM + c];
    }
    if (tid < 32) {
        float bb = g_ba[(size_t)bs*64 + tid];
        g_beta[((size_t)b*HVv + tid)*S_ + s] = 1.f / (1.f + expf(-bb));
    } else if (tid < 64) {
        int h = tid - 32;
        float a = g_ba[(size_t)bs*64 + 32 + h] + dtb[h];
        float sp = (a > 20.f) ? a : log1pf(expf(a));
        g_g[((size_t)b*HVv + h)*S_ + s] = -expf(Alog[h]) * sp;
    }
}

__device__ __forceinline__ float dot128(const float* a, const float* b) {
    float s0 = 0.f, s1 = 0.f, s2 = 0.f, s3 = 0.f;
#pragma unroll
    for (int d = 0; d < 128; d += 4) {
        s0 += a[d]   * b[d];
        s1 += a[d+1] * b[d+1];
        s2 += a[d+2] * b[d+2];
        s3 += a[d+3] * b[d+3];
    }
    return (s0 + s1) + (s2 + s3);
}

// -------- per-(b,h,chunk) intra-chunk quantities --------
__global__ void chunk_prep() {
    extern __shared__ float sm[];
    float* q_s  = sm;
    float* k_s  = q_s  + 64*SP;
    float* vb_s = k_s  + 64*SP;
    float* A_s  = vb_s + 64*SP;
    float* T_s  = A_s  + 64*64;
    __shared__ float gc_s[64], beta_s[64], kbe_s[64];

    int blk = blockIdx.x;
    int n = blk & 31, h = (blk >> 5) & 31, b = blk >> 10;
    int hq = h >> 1;
    int tid = threadIdx.x;

    size_t qk_off = (((size_t)b*HKq + hq)*S_ + (size_t)n*CHUNK) * DKd;
    size_t v_off  = (((size_t)b*HVv + h )*S_ + (size_t)n*CHUNK) * DVd;
    size_t gb_off = ((size_t)b*HVv + h)*S_ + (size_t)n*CHUNK;

    if (tid < 64) { gc_s[tid] = g_g[gb_off + tid]; beta_s[tid] = g_beta[gb_off + tid]; }
    __syncthreads();
    if (tid == 0) { for (int i = 1; i < 64; i++) gc_s[i] += gc_s[i - 1]; }
    __syncthreads();
    if (tid < 64) {
        g_gc[gb_off + tid] = gc_s[tid];
        kbe_s[tid] = beta_s[tid] * expf(gc_s[tid]);
    }
    for (int i = tid; i < 64 * 128; i += 256) {
        int r = i >> 7, d = i & 127;
        q_s [r*SP + d] = g_q[qk_off + i];
        k_s [r*SP + d] = g_k[qk_off + i];
        vb_s[r*SP + d] = g_v[v_off + i] * beta_s[r];
    }
    __syncthreads();

    for (int i = tid; i < 4096; i += 256) {
        int c = i >> 6, j = i & 63;
        float val = 0.f;
        if (j < c)
            val = dot128(&k_s[c*SP], &k_s[j*SP]) * beta_s[c] * expf(gc_s[c] - gc_s[j]);
        A_s[i] = val;
    }
    __syncthreads();

    if (tid < 64) {
        int col = tid;
        for (int c = 0; c < 64; c++) {
            float ssum = (c == col) ? 1.f : 0.f;
            for (int j = col; j < c; j++) ssum -= A_s[c*64 + j] * T_s[j*65 + col];
            T_s[c*65 + col] = (c >= col) ? ssum : 0.f;
        }
    }
    __syncthreads();

    size_t kcd_off = (((size_t)b*HVv + h)*S_ + (size_t)n*CHUNK) * DKd;
    for (int i = tid; i < 64 * 128; i += 256) {
        int c = i >> 7, d = i & 127;
        float av = 0.f, ak = 0.f;
#pragma unroll 4
        for (int j = 0; j <= c; j++) {
            float t = T_s[c*65 + j];
            av += t * vb_s[j*SP + d];
            ak += t * k_s[j*SP + d] * kbe_s[j];
        }
        g_vadj[v_off + i]  = av;
        g_kcd [kcd_off + i] = ak;
    }
    size_t at_off = gb_off * CHUNK;
    for (int i = tid; i < 4096; i += 256) {
        int c = i >> 6, j = i & 63;
        float val = 0.f;
        if (j <= c)
            val = dot128(&q_s[c*SP], &k_s[j*SP]) * expf(gc_s[c] - gc_s[j]);
        g_attn[at_off + i] = val;
    }
}

// -------- sequential scan over chunks --------
__global__ void scan_kernel() {
    extern __shared__ float sm[];
    float* q_s    = sm;
    float* k_s    = q_s   + 64*SP;
    float* kcd_s  = k_s   + 64*SP;
    float* attn_s = kcd_s + 64*SP;
    float* vadj_s = attn_s + 4096;
    float* vnew_s = vadj_s + 2048;
    float* st     = vnew_s + 2048;
    __shared__ float gc_s[64], eg_s[64], ek_s[64];

    int bh = blockIdx.x, dvt = blockIdx.y;
    int b = bh >> 5, h = bh & 31, hq = h >> 1;
    int tid = threadIdx.x;
    int dv = tid & 31, part = tid >> 5;

    for (int i = tid; i < 128 * 32; i += 256) st[i] = 0.f;

    for (int n = 0; n < NCH; n++) {
        size_t qk_off = (((size_t)b*HKq + hq)*S_ + (size_t)n*CHUNK) * DKd;
        size_t kv_off = (((size_t)b*HVv + h )*S_ + (size_t)n*CHUNK) * DKd;
        size_t gb_off = ((size_t)b*HVv + h)*S_ + (size_t)n*CHUNK;
        __syncthreads();
        for (int i = tid; i < 64 * 128; i += 256) {
            int r = i >> 7, d = i & 127;
            q_s  [r*SP + d] = g_q  [qk_off + i];
            k_s  [r*SP + d] = g_k  [qk_off + i];
            kcd_s[r*SP + d] = g_kcd[kv_off + i];
        }
        for (int i = tid; i < 4096; i += 256) attn_s[i] = g_attn[gb_off*CHUNK + i];
        for (int i = tid; i < 2048; i += 256) {
            int c = i >> 5, d = i & 31;
            vadj_s[i] = g_vadj[kv_off + (size_t)c*128 + dvt*32 + d];
        }
        if (tid < 64) { float gv = g_gc[gb_off + tid]; gc_s[tid] = gv; eg_s[tid] = expf(gv); }
        __syncthreads();
        if (tid < 64) ek_s[tid] = expf(gc_s[63] - gc_s[tid]);

        float acc[8];
#pragma unroll
        for (int ii = 0; ii < 8; ii++) acc[ii] = vadj_s[(part + ii*8)*32 + dv];
        for (int dk = 0; dk < 128; dk++) {
            float sv = st[dk*32 + dv];
#pragma unroll
            for (int ii = 0; ii < 8; ii++) acc[ii] -= kcd_s[(part + ii*8)*SP + dk] * sv;
        }
#pragma unroll
        for (int ii = 0; ii < 8; ii++) vnew_s[(part + ii*8)*32 + dv] = acc[ii];
        __syncthreads();

        float oc[8];
#pragma unroll
        for (int ii = 0; ii < 8; ii++) oc[ii] = 0.f;
        for (int dk = 0; dk < 128; dk++) {
            float sv = st[dk*32 + dv];
#pragma unroll
            for (int ii = 0; ii < 8; ii++) oc[ii] += q_s[(part + ii*8)*SP + dk] * sv;
        }
#pragma unroll
        for (int ii = 0; ii < 8; ii++) oc[ii] *= eg_s[part + ii*8];
        for (int j = 0; j < 64; j++) {
            float vv = vnew_s[j*32 + dv];
#pragma unroll
            for (int ii = 0; ii < 8; ii++) oc[ii] += attn_s[(part + ii*8)*64 + j] * vv;
        }
        size_t o_base = ((size_t)b*S_ + (size_t)n*CHUNK) * VALUE_DIM + (size_t)h*DVd + dvt*32 + dv;
#pragma unroll
        for (int ii = 0; ii < 8; ii++)
            g_o[o_base + (size_t)(part + ii*8) * VALUE_DIM] = oc[ii];
        __syncthreads();

        float egl = eg_s[63];
        float sa[16];
#pragma unroll
        for (int ii = 0; ii < 16; ii++) sa[ii] = st[(part + ii*8)*32 + dv] * egl;
        for (int c = 0; c < 64; c++) {
            float vv = vnew_s[c*32 + dv] * ek_s[c];
#pragma unroll
            for (int ii = 0; ii < 16; ii++) sa[ii] += k_s[c*SP + (part + ii*8)] * vv;
        }
#pragma unroll
        for (int ii = 0; ii < 16; ii++) st[(part + ii*8)*32 + dv] = sa[ii];
    }
}

// -------- gated RMSNorm --------
__global__ void gated_norm(const float* __restrict__ nw) {
    int bs = blockIdx.x;
    int warp = threadIdx.x >> 5, lane = threadIdx.x & 31;
    for (int h = warp; h < HVv; h += 8) {
        size_t off = (size_t)bs * VALUE_DIM + (size_t)h * DVd;
        float4 v = ((float4*)(g_o + off))[lane];
        float ss = v.x*v.x + v.y*v.y + v.z*v.z + v.w*v.w;
#pragma unroll
        for (int o = 16; o; o >>= 1) ss += __shfl_xor_sync(~0u, ss, o);
        float r = rsqrtf(ss / 128.f + 1e-6f);
        size_t zoff = (size_t)bs * QKVZ_N + 2*KEY_DIM + VALUE_DIM + (size_t)h * DVd;
        float4 z = ((const float4*)(g_qkvz + zoff))[lane];
        float4 w = ((const float4*)nw)[lane];
        v.x = v.x * r * w.x * (z.x / (1.f + expf(-z.x)));
        v.y = v.y * r * w.y * (z.y / (1.f + expf(-z.y)));
        v.z = v.z * r * w.z * (z.z / (1.f + expf(-z.z)));
        v.w = v.w * r * w.w * (z.w / (1.f + expf(-z.w)));
        ((float4*)(g_o + off))[lane] = v;
    }
}

// ---------------- launcher ----------------
extern "C" void kernel_launch(void* const* d_in, const int* in_sizes, int n_in,
                              void* d_out, int out_size) {
    const float* hidden = (const float*)d_in[0];
    const float* Wqkvz  = (const float*)d_in[1];
    const float* Wba    = (const float*)d_in[2];
    const float* convw  = (const float*)d_in[3];
    const float* dtb    = (const float*)d_in[4];
    const float* Alog   = (const float*)d_in[5];
    const float* nw     = (const float*)d_in[6];
    const float* Wout   = (const float*)d_in[7];
    float* out = (float*)d_out;

    float *qkvz_p, *o_p;
    __half *p_p, *q_p, *r_p, *s_p;
    cudaGetSymbolAddress((void**)&qkvz_p, g_qkvz);
    cudaGetSymbolAddress((void**)&o_p, g_o);
    cudaGetSymbolAddress((void**)&p_p, g_p);
    cudaGetSymbolAddress((void**)&q_p, g_q2);
    cudaGetSymbolAddress((void**)&r_p, g_r);
    cudaGetSymbolAddress((void**)&s_p, g_s2);

    const int SMEM3 = (3*64*SP + 64*64 + 64*65) * 4;
    const int SMEM4 = (3*64*SP + 4096 + 2048 + 2048 + 128*32) * 4;
    const int SMEM_MM = 3 * STG2 * 2;               // 3 stages * 30720 B = 92160
    cudaFuncSetAttribute(chunk_prep, cudaFuncAttributeMaxDynamicSharedMemorySize, SMEM3);
    cudaFuncSetAttribute(scan_kernel, cudaFuncAttributeMaxDynamicSharedMemorySize, SMEM4);
    cudaFuncSetAttribute(mmgemm, cudaFuncAttributeMaxDynamicSharedMemorySize, SMEM_MM);

    // --- GEMM1: qkvz = hidden @ W_qkvz  (split fp16, HMMA; bm fast for L2 reuse) ---
    cvt_h<<<(BSz*(size_t)HID)/1024, 256>>>(hidden, p_p);
    cvt_split_T<<<dim3(QKVZ_N/32, HID/32), dim3(32,8)>>>(Wqkvz, r_p, s_p, HID, QKVZ_N);
    mmgemm<<<dim3(BSz/128, QKVZ_N/128), 256, SMEM_MM>>>(p_p, r_p, s_p, qkvz_p, BSz, QKVZ_N, HID);

    // --- small BA projection (split-K + reduce) ---
    gemm_ba_part<<<dim3(BSz/64, 8), 256>>>(hidden, Wba);
    gemm_ba_reduce<<<(BSz*64)/256, 256>>>();

    // --- conv + gates, chunk prep, scan, norm ---
    conv_gate<<<BSz, 256>>>(convw, dtb, Alog);
    chunk_prep<<<B_*HVv*NCH, 256, SMEM3>>>();
    scan_kernel<<<dim3(B_*HVv, 4), 256, SMEM4>>>();
    gated_norm<<<BSz, 256>>>(nw);

    // --- GEMM2: out = o @ W_out (split fp16, HMMA; bm fast) ---
    cvt_h<<<(BSz*(size_t)VALUE_DIM)/1024, 256>>>(o_p, r_p);
    cvt_split_T<<<dim3(HID/32, VALUE_DIM/32), dim3(32,8)>>>(Wout, p_p, q_p, VALUE_DIM, HID);
    mmgemm<<<dim3(BSz/128, HID/128), 256, SMEM_MM>>>(r_p, p_p, q_p, out, BSz, HID, VALUE_DIM);
}

// round 6
// speedup vs baseline: 2.7278x; 1.3135x over previous
#include <cuda_runtime.h>
#include <cuda_bf16.h>
#include <cuda_fp16.h>
#include <math.h>
#include <stdint.h>

// ---------------- problem constants ----------------
#define B_   2
#define S_   2048
#define HID  2048
#define HKq  16
#define HVv  32
#define DKd  128
#define DVd  128
#define KC   4
#define CHUNK 64
#define NCH  (S_/CHUNK)          // 32
#define KEY_DIM 2048
#define VALUE_DIM 4096
#define CONV_DIM 8192
#define QKVZ_N 12288
#define BSz  (B_*S_)             // 4096
#define QSCALE 0.08838834764831845f   // DK^-0.5
#define SP 129                   // padded smem row stride for 128-wide fp32 tiles

// ---------------- scratch (static device memory; no allocations) ------------
__device__ float g_qkvz[(size_t)BSz*QKVZ_N];               // [BS,12288] q|k|v|z
__device__ float g_ba[(size_t)BSz*64];
__device__ float g_bap[(size_t)8*BSz*64];                  // split-K partials
__device__ float g_q[(size_t)B_*HKq*S_*DKd];
__device__ float g_k[(size_t)B_*HKq*S_*DKd];
__device__ float g_v[(size_t)B_*HVv*S_*DVd];
__device__ float g_g[(size_t)B_*HVv*S_];
__device__ float g_beta[(size_t)B_*HVv*S_];
__device__ float g_gc[(size_t)B_*HVv*S_];
__device__ float g_vadj[(size_t)B_*HVv*S_*DVd];
__device__ float g_kcd[(size_t)B_*HVv*S_*DKd];
__device__ float g_attn[(size_t)B_*HVv*S_*CHUNK];
__device__ float g_o[(size_t)BSz*VALUE_DIM];

// fp16 operand buffers (reused across the two GEMMs)
__device__ __half g_p [(size_t)8388608];    // A1     / B2t
__device__ __half g_r [(size_t)25165824];   // B1t    / A2

__device__ __forceinline__ uint32_t smem_u32(const void* p) {
    uint32_t a;
    asm("{ .reg .u64 t; cvta.to.shared.u64 t, %1; cvt.u32.u64 %0, t; }" : "=r"(a) : "l"(p));
    return a;
}

// ---------------- fp32 -> fp16 (elementwise, float4) ----------------
__global__ void cvt_h(const float* __restrict__ X, __half* __restrict__ H) {
    size_t i = ((size_t)blockIdx.x * 256 + threadIdx.x) * 4;
    float4 v = *(const float4*)&X[i];
    __half2 h0 = __floats2half2_rn(v.x, v.y);
    __half2 h1 = __floats2half2_rn(v.z, v.w);
    uint2 hv;
    hv.x = *(uint32_t*)&h0; hv.y = *(uint32_t*)&h1;
    *(uint2*)&H[i] = hv;
}

// ---------------- fp32 [K,N] -> fp16 [N,K] transpose ----------------
__global__ void cvt_T(const float* __restrict__ W, __half* __restrict__ Ht, int K, int N) {
    __shared__ float tile[32][33];
    int n0 = blockIdx.x * 32, k0 = blockIdx.y * 32;
    int tx = threadIdx.x, ty = threadIdx.y;   // 32 x 8
#pragma unroll
    for (int j = 0; j < 32; j += 8)
        tile[ty + j][tx] = W[(size_t)(k0 + ty + j) * N + n0 + tx];
    __syncthreads();
#pragma unroll
    for (int j = 0; j < 32; j += 8)
        Ht[(size_t)(n0 + ty + j) * K + k0 + tx] = __float2half_rn(tile[tx][ty + j]);
}

// ============ fp16 HMMA GEMM: C[M,N] = A[M,K] @ Bt[N,K]^T (fp32 accum) ============
// 128x128 CTA tile, BK=32, 4-stage cp.async, 2 CTAs/SM (82KB smem/CTA).
#define PSH 40                     // padded fp16 row stride (conflict-free ldmatrix)
#define TEN2 (128*PSH)             // elements per tensor tile (5120)
#define STG1 (2*TEN2)              // elements per stage (A|B)
#define NSTG 4

__device__ __forceinline__ void mma_f16(float* c, const uint32_t* a, const uint32_t* b) {
    asm volatile("mma.sync.aligned.m16n8k16.row.col.f32.f16.f16.f32 "
                 "{%0,%1,%2,%3}, {%4,%5,%6,%7}, {%8,%9}, {%0,%1,%2,%3};"
                 : "+f"(c[0]), "+f"(c[1]), "+f"(c[2]), "+f"(c[3])
                 : "r"(a[0]), "r"(a[1]), "r"(a[2]), "r"(a[3]), "r"(b[0]), "r"(b[1]));
}
__device__ __forceinline__ void ldmx4(uint32_t* r, uint32_t addr) {
    asm volatile("ldmatrix.sync.aligned.m8n8.x4.shared.b16 {%0,%1,%2,%3}, [%4];"
                 : "=r"(r[0]), "=r"(r[1]), "=r"(r[2]), "=r"(r[3]) : "r"(addr));
}

__device__ __forceinline__ void stage_load(uint32_t sbase_b, int stage,
    const __half* a0, const __half* b0, int K, int kt, int tid)
{
    const __half* gp[2] = {a0, b0};
    uint32_t st_b = sbase_b + (uint32_t)stage * (STG1 * 2);
#pragma unroll
    for (int t = 0; t < 2; t++) {
        uint32_t tb = st_b + (uint32_t)t * (TEN2 * 2);
#pragma unroll
        for (int j = 0; j < 2; j++) {
            int idx = j * 256 + tid;
            int row = idx >> 2, c16 = idx & 3;
            uint32_t sa = tb + (uint32_t)(row * (PSH*2) + c16 * 16);
            const void* ga = gp[t] + (size_t)row * K + (size_t)kt * 32 + c16 * 8;
            asm volatile("cp.async.cg.shared.global [%0], [%1], 16;" :: "r"(sa), "l"(ga));
        }
    }
    asm volatile("cp.async.commit_group;" ::: "memory");
}

__global__ void __launch_bounds__(256, 2) mmgemm(
    const __half* __restrict__ Ah, const __half* __restrict__ Bh,
    float* __restrict__ C, int M, int N, int K)
{
    extern __shared__ __half smem[];
    uint32_t sbase = smem_u32(smem);
    int tid = threadIdx.x, lane = tid & 31, wid = tid >> 5;
    int warpM = wid >> 2, warpN = wid & 3;      // 2 x 4 warp grid
    int bm = blockIdx.x, bn = blockIdx.y;       // bm fast
    const int T = K >> 5;

    const __half* a0 = Ah + (size_t)bm * 128 * K;
    const __half* b0 = Bh + (size_t)bn * 128 * K;

    int g = lane >> 3, lr = lane & 7;
    uint32_t aoff = (uint32_t)((warpM*64 + (g&1)*8 + lr) * PSH + (g>>1)*8);
    uint32_t boff = (uint32_t)((warpN*32 + (g>>1)*8 + lr) * PSH + (g&1)*8);

    float acc[4][4][4];
#pragma unroll
    for (int i = 0; i < 4; i++)
#pragma unroll
        for (int j = 0; j < 4; j++)
#pragma unroll
            for (int r = 0; r < 4; r++) acc[i][j][r] = 0.f;

    stage_load(sbase, 0, a0, b0, K, 0, tid);
    stage_load(sbase, 1, a0, b0, K, 1, tid);
    stage_load(sbase, 2, a0, b0, K, 2, tid);

    for (int kt = 0; kt < T; kt++) {
        int rem = T - 1 - kt;
        if (rem >= 2)      asm volatile("cp.async.wait_group 2;" ::: "memory");
        else if (rem == 1) asm volatile("cp.async.wait_group 1;" ::: "memory");
        else               asm volatile("cp.async.wait_group 0;" ::: "memory");
        __syncthreads();
        if (kt + 3 < T) stage_load(sbase, (kt + 3) % NSTG, a0, b0, K, kt + 3, tid);

        uint32_t st = sbase + (uint32_t)(kt % NSTG) * (STG1 * 2);
        uint32_t sA = st, sB = st + TEN2*2;
#pragma unroll
        for (int ks = 0; ks < 2; ks++) {
            int kk = ks * 16;
            uint32_t ah[4][4], bh[4][2];
#pragma unroll
            for (int mi = 0; mi < 4; mi++)
                ldmx4(ah[mi], sA + (aoff + mi*16*PSH + kk) * 2);
#pragma unroll
            for (int p = 0; p < 2; p++) {
                uint32_t rh[4];
                ldmx4(rh, sB + (boff + p*16*PSH + kk) * 2);
                bh[2*p][0] = rh[0]; bh[2*p][1] = rh[1];
                bh[2*p+1][0] = rh[2]; bh[2*p+1][1] = rh[3];
            }
#pragma unroll
            for (int mi = 0; mi < 4; mi++)
#pragma unroll
                for (int ni = 0; ni < 4; ni++)
                    mma_f16(acc[mi][ni], ah[mi], bh[ni]);
        }
        __syncthreads();
    }

    int rr = lane >> 2, cc = (lane & 3) * 2;
#pragma unroll
    for (int mi = 0; mi < 4; mi++) {
        int row0 = bm * 128 + warpM * 64 + mi * 16 + rr;
#pragma unroll
        for (int ni = 0; ni < 4; ni++) {
            int col = bn * 128 + warpN * 32 + ni * 8 + cc;
            float2 v0 = make_float2(acc[mi][ni][0], acc[mi][ni][1]);
            float2 v1 = make_float2(acc[mi][ni][2], acc[mi][ni][3]);
            *(float2*)&C[(size_t)row0 * N + col]       = v0;
            *(float2*)&C[(size_t)(row0 + 8) * N + col] = v1;
        }
    }
}

// ------------- BA projection split-K: [BS,2048]@[2048,64] -> partials -------------
__global__ void gemm_ba_part(const float* __restrict__ X, const float* __restrict__ W) {
    __shared__ float Xs[64][65];
    __shared__ float Ws[64][64];
    int tid = threadIdx.x;
    int row0 = blockIdx.x * 64;
    int kbase = blockIdx.y * 256;
    int col = (tid & 15) * 4;
    int r0 = (tid >> 4) * 4;
    float acc[4][4] = {};
    for (int k0 = kbase; k0 < kbase + 256; k0 += 64) {
#pragma unroll
        for (int j = 0; j < 16; j++) {
            int idx = j * 256 + tid;
            int r = idx >> 6, kk = idx & 63;
            Xs[r][kk] = X[(size_t)(row0 + r) * HID + k0 + kk];
        }
#pragma unroll
        for (int j = 0; j < 16; j++) {
            int idx = j * 256 + tid;
            int kk = idx >> 6, c = idx & 63;
            Ws[kk][c] = W[(size_t)(k0 + kk) * 64 + c];
        }
        __syncthreads();
#pragma unroll 8
        for (int kk = 0; kk < 64; kk++) {
            float4 b = *(float4*)&Ws[kk][col];
#pragma unroll
            for (int r = 0; r < 4; r++) {
                float a = Xs[r0 + r][kk];
                acc[r][0] += a*b.x; acc[r][1] += a*b.y; acc[r][2] += a*b.z; acc[r][3] += a*b.w;
            }
        }
        __syncthreads();
    }
    float* dst = g_bap + (size_t)blockIdx.y * BSz * 64;
#pragma unroll
    for (int r = 0; r < 4; r++)
        *(float4*)&dst[(size_t)(row0 + r0 + r) * 64 + col] =
            make_float4(acc[r][0], acc[r][1], acc[r][2], acc[r][3]);
}
__global__ void gemm_ba_reduce() {
    size_t i = (size_t)blockIdx.x * 256 + threadIdx.x;
    float s = 0.f;
#pragma unroll
    for (int p = 0; p < 8; p++) s += g_bap[(size_t)p * BSz * 64 + i];
    g_ba[i] = s;
}

// -------- conv + silu + l2norm + head transpose + gates --------
__global__ void conv_gate(const float* __restrict__ cw, const float* __restrict__ dtb,
                          const float* __restrict__ Alog) {
    int bs = blockIdx.x;
    int b = bs / S_, s = bs % S_;
    int tid = threadIdx.x;
    __shared__ float cs[CONV_DIM];
    __shared__ float hsum[32];
    const float* base = g_qkvz + (size_t)bs * QKVZ_N;

    for (int c = tid; c < CONV_DIM; c += 256) {
        float w0 = cw[c*4+0], w1 = cw[c*4+1], w2 = cw[c*4+2], w3 = cw[c*4+3];
        float acc = base[c] * w3;
        if (s >= 1) acc += base[c - (size_t)QKVZ_N] * w2;
        if (s >= 2) acc += base[c - (size_t)2*QKVZ_N] * w1;
        if (s >= 3) acc += base[c - (size_t)3*QKVZ_N] * w0;
        cs[c] = acc / (1.f + __expf(-acc));
    }
    __syncthreads();
    int warp = tid >> 5, lane = tid & 31;
    for (int h = warp; h < 32; h += 8) {
        float ss = 0.f;
        for (int d = lane; d < 128; d += 32) { float v = cs[h*128 + d]; ss += v * v; }
#pragma unroll
        for (int o = 16; o; o >>= 1) ss += __shfl_xor_sync(~0u, ss, o);
        if (!lane) hsum[h] = rsqrtf(ss + 1e-6f);
    }
    __syncthreads();
    for (int c = tid; c < KEY_DIM; c += 256) {
        int h = c >> 7, d = c & 127;
        g_q[(((size_t)b*HKq + h)*S_ + s)*DKd + d] = cs[c] * hsum[h] * QSCALE;
    }
    for (int c = tid; c < KEY_DIM; c += 256) {
        int h = c >> 7, d = c & 127;
        g_k[(((size_t)b*HKq + h)*S_ + s)*DKd + d] = cs[KEY_DIM + c] * hsum[16 + h];
    }
    for (int c = tid; c < VALUE_DIM; c += 256) {
        int h = c >> 7, d = c & 127;
        g_v[(((size_t)b*HVv + h)*S_ + s)*DVd + d] = cs[2*KEY_DIM + c];
    }
    if (tid < 32) {
        float bb = g_ba[(size_t)bs*64 + tid];
        g_beta[((size_t)b*HVv + tid)*S_ + s] = 1.f / (1.f + expf(-bb));
    } else if (tid < 64) {
        int h = tid - 32;
        float a = g_ba[(size_t)bs*64 + 32 + h] + dtb[h];
        float sp = (a > 20.f) ? a : log1pf(expf(a));
        g_g[((size_t)b*HVv + h)*S_ + s] = -expf(Alog[h]) * sp;
    }
}

__device__ __forceinline__ float dot128(const float* a, const float* b) {
    float s0 = 0.f, s1 = 0.f, s2 = 0.f, s3 = 0.f;
#pragma unroll
    for (int d = 0; d < 128; d += 4) {
        s0 += a[d]   * b[d];
        s1 += a[d+1] * b[d+1];
        s2 += a[d+2] * b[d+2];
        s3 += a[d+3] * b[d+3];
    }
    return (s0 + s1) + (s2 + s3);
}

// -------- per-(b,h,chunk) intra-chunk quantities --------
__global__ void chunk_prep() {
    extern __shared__ float sm[];
    float* q_s  = sm;
    float* k_s  = q_s  + 64*SP;
    float* vb_s = k_s  + 64*SP;
    float* A_s  = vb_s + 64*SP;
    float* T_s  = A_s  + 64*64;
    __shared__ float gc_s[64], beta_s[64], kbe_s[64];

    int blk = blockIdx.x;
    int n = blk & 31, h = (blk >> 5) & 31, b = blk >> 10;
    int hq = h >> 1;
    int tid = threadIdx.x;

    size_t qk_off = (((size_t)b*HKq + hq)*S_ + (size_t)n*CHUNK) * DKd;
    size_t v_off  = (((size_t)b*HVv + h )*S_ + (size_t)n*CHUNK) * DVd;
    size_t gb_off = ((size_t)b*HVv + h)*S_ + (size_t)n*CHUNK;

    if (tid < 64) { gc_s[tid] = g_g[gb_off + tid]; beta_s[tid] = g_beta[gb_off + tid]; }
    __syncthreads();
    if (tid == 0) { for (int i = 1; i < 64; i++) gc_s[i] += gc_s[i - 1]; }
    __syncthreads();
    if (tid < 64) {
        g_gc[gb_off + tid] = gc_s[tid];
        kbe_s[tid] = beta_s[tid] * expf(gc_s[tid]);
    }
    for (int i = tid; i < 64 * 128; i += 256) {
        int r = i >> 7, d = i & 127;
        q_s [r*SP + d] = g_q[qk_off + i];
        k_s [r*SP + d] = g_k[qk_off + i];
        vb_s[r*SP + d] = g_v[v_off + i] * beta_s[r];
    }
    __syncthreads();

    for (int i = tid; i < 4096; i += 256) {
        int c = i >> 6, j = i & 63;
        float val = 0.f;
        if (j < c)
            val = dot128(&k_s[c*SP], &k_s[j*SP]) * beta_s[c] * expf(gc_s[c] - gc_s[j]);
        A_s[i] = val;
    }
    __syncthreads();

    if (tid < 64) {
        int col = tid;
        for (int c = 0; c < 64; c++) {
            float ssum = (c == col) ? 1.f : 0.f;
            for (int j = col; j < c; j++) ssum -= A_s[c*64 + j] * T_s[j*65 + col];
            T_s[c*65 + col] = (c >= col) ? ssum : 0.f;
        }
    }
    __syncthreads();

    size_t kcd_off = (((size_t)b*HVv + h)*S_ + (size_t)n*CHUNK) * DKd;
    for (int i = tid; i < 64 * 128; i += 256) {
        int c = i >> 7, d = i & 127;
        float av = 0.f, ak = 0.f;
#pragma unroll 4
        for (int j = 0; j <= c; j++) {
            float t = T_s[c*65 + j];
            av += t * vb_s[j*SP + d];
            ak += t * k_s[j*SP + d] * kbe_s[j];
        }
        g_vadj[v_off + i]  = av;
        g_kcd [kcd_off + i] = ak;
    }
    size_t at_off = gb_off * CHUNK;
    for (int i = tid; i < 4096; i += 256) {
        int c = i >> 6, j = i & 63;
        float val = 0.f;
        if (j <= c)
            val = dot128(&q_s[c*SP], &k_s[j*SP]) * expf(gc_s[c] - gc_s[j]);
        g_attn[at_off + i] = val;
    }
}

// -------- sequential scan over chunks; 512 threads, dv-tile 64, grid (64,2) --------
__global__ void __launch_bounds__(512, 1) scan_kernel() {
    extern __shared__ float sm[];
    float* q_s    = sm;                    // 64*SP
    float* k_s    = q_s   + 64*SP;
    float* kcd_s  = k_s   + 64*SP;
    float* attn_s = kcd_s + 64*SP;         // 4096
    float* vadj_s = attn_s + 4096;         // 64*64
    float* vnew_s = vadj_s + 4096;         // 64*64
    float* st     = vnew_s + 4096;         // 128*64
    __shared__ float gc_s[64], eg_s[64], ek_s[64];

    int bh = blockIdx.x, dvt = blockIdx.y;   // dvt in {0,1}
    int b = bh >> 5, h = bh & 31, hq = h >> 1;
    int tid = threadIdx.x;
    int dv = tid & 63, part = tid >> 6;      // part 0..7

    for (int i = tid; i < 128 * 64; i += 512) st[i] = 0.f;

    for (int n = 0; n < NCH; n++) {
        size_t qk_off = (((size_t)b*HKq + hq)*S_ + (size_t)n*CHUNK) * DKd;
        size_t kv_off = (((size_t)b*HVv + h )*S_ + (size_t)n*CHUNK) * DKd;
        size_t gb_off = ((size_t)b*HVv + h)*S_ + (size_t)n*CHUNK;
        __syncthreads();
        for (int i = tid; i < 64 * 128; i += 512) {
            int r = i >> 7, d = i & 127;
            q_s  [r*SP + d] = g_q  [qk_off + i];
            k_s  [r*SP + d] = g_k  [qk_off + i];
            kcd_s[r*SP + d] = g_kcd[kv_off + i];
        }
        for (int i = tid; i < 4096; i += 512) attn_s[i] = g_attn[gb_off*CHUNK + i];
        for (int i = tid; i < 4096; i += 512) {
            int c = i >> 6, d = i & 63;
            vadj_s[i] = g_vadj[kv_off + (size_t)c*128 + dvt*64 + d];
        }
        if (tid < 64) { float gv = g_gc[gb_off + tid]; gc_s[tid] = gv; eg_s[tid] = expf(gv); }
        __syncthreads();
        if (tid < 64) ek_s[tid] = expf(gc_s[63] - gc_s[tid]);

        // v_new = v_adj - kcd @ state
        float acc[8];
#pragma unroll
        for (int ii = 0; ii < 8; ii++) acc[ii] = vadj_s[(part + ii*8)*64 + dv];
        for (int dk = 0; dk < 128; dk++) {
            float sv = st[dk*64 + dv];
#pragma unroll
            for (int ii = 0; ii < 8; ii++) acc[ii] -= kcd_s[(part + ii*8)*SP + dk] * sv;
        }
#pragma unroll
        for (int ii = 0; ii < 8; ii++) vnew_s[(part + ii*8)*64 + dv] = acc[ii];
        __syncthreads();

        // o = (q*exp(gc)) @ state + attn @ v_new
        float oc[8];
#pragma unroll
        for (int ii = 0; ii < 8; ii++) oc[ii] = 0.f;
        for (int dk = 0; dk < 128; dk++) {
            float sv = st[dk*64 + dv];
#pragma unroll
            for (int ii = 0; ii < 8; ii++) oc[ii] += q_s[(part + ii*8)*SP + dk] * sv;
        }
#pragma unroll
        for (int ii = 0; ii < 8; ii++) oc[ii] *= eg_s[part + ii*8];
        for (int j = 0; j < 64; j++) {
            float vv = vnew_s[j*64 + dv];
#pragma unroll
            for (int ii = 0; ii < 8; ii++) oc[ii] += attn_s[(part + ii*8)*64 + j] * vv;
        }
        size_t o_base = ((size_t)b*S_ + (size_t)n*CHUNK) * VALUE_DIM + (size_t)h*DVd + dvt*64 + dv;
#pragma unroll
        for (int ii = 0; ii < 8; ii++)
            g_o[o_base + (size_t)(part + ii*8) * VALUE_DIM] = oc[ii];
        __syncthreads();

        // state = state*exp(g_last) + (k*exp(g_last-gc))^T @ v_new
        float egl = eg_s[63];
        float sa[16];
#pragma unroll
        for (int ii = 0; ii < 16; ii++) sa[ii] = st[(part + ii*8)*64 + dv] * egl;
        for (int c = 0; c < 64; c++) {
            float vv = vnew_s[c*64 + dv] * ek_s[c];
#pragma unroll
            for (int ii = 0; ii < 16; ii++) sa[ii] += k_s[c*SP + (part + ii*8)] * vv;
        }
#pragma unroll
        for (int ii = 0; ii < 16; ii++) st[(part + ii*8)*64 + dv] = sa[ii];
    }
}

// -------- gated RMSNorm --------
__global__ void gated_norm(const float* __restrict__ nw) {
    int bs = blockIdx.x;
    int warp = threadIdx.x >> 5, lane = threadIdx.x & 31;
    for (int h = warp; h < HVv; h += 8) {
        size_t off = (size_t)bs * VALUE_DIM + (size_t)h * DVd;
        float4 v = ((float4*)(g_o + off))[lane];
        float ss = v.x*v.x + v.y*v.y + v.z*v.z + v.w*v.w;
#pragma unroll
        for (int o = 16; o; o >>= 1) ss += __shfl_xor_sync(~0u, ss, o);
        float r = rsqrtf(ss / 128.f + 1e-6f);
        size_t zoff = (size_t)bs * QKVZ_N + 2*KEY_DIM + VALUE_DIM + (size_t)h * DVd;
        float4 z = ((const float4*)(g_qkvz + zoff))[lane];
        float4 w = ((const float4*)nw)[lane];
        v.x = v.x * r * w.x * (z.x / (1.f + expf(-z.x)));
        v.y = v.y * r * w.y * (z.y / (1.f + expf(-z.y)));
        v.z = v.z * r * w.z * (z.z / (1.f + expf(-z.z)));
        v.w = v.w * r * w.w * (z.w / (1.f + expf(-z.w)));
        ((float4*)(g_o + off))[lane] = v;
    }
}

// ---------------- launcher ----------------
extern "C" void kernel_launch(void* const* d_in, const int* in_sizes, int n_in,
                              void* d_out, int out_size) {
    const float* hidden = (const float*)d_in[0];
    const float* Wqkvz  = (const float*)d_in[1];
    const float* Wba    = (const float*)d_in[2];
    const float* convw  = (const float*)d_in[3];
    const float* dtb    = (const float*)d_in[4];
    const float* Alog   = (const float*)d_in[5];
    const float* nw     = (const float*)d_in[6];
    const float* Wout   = (const float*)d_in[7];
    float* out = (float*)d_out;

    float *qkvz_p, *o_p;
    __half *p_p, *r_p;
    cudaGetSymbolAddress((void**)&qkvz_p, g_qkvz);
    cudaGetSymbolAddress((void**)&o_p, g_o);
    cudaGetSymbolAddress((void**)&p_p, g_p);
    cudaGetSymbolAddress((void**)&r_p, g_r);

    const int SMEM3 = (3*64*SP + 64*64 + 64*65) * 4;
    const int SMEM4 = (3*64*SP + 4096 + 4096 + 4096 + 128*64) * 4;   // 180992
    const int SMEM_MM = NSTG * STG1 * 2;            // 4 stages * 20480 B = 81920
    cudaFuncSetAttribute(chunk_prep, cudaFuncAttributeMaxDynamicSharedMemorySize, SMEM3);
    cudaFuncSetAttribute(scan_kernel, cudaFuncAttributeMaxDynamicSharedMemorySize, SMEM4);
    cudaFuncSetAttribute(mmgemm, cudaFuncAttributeMaxDynamicSharedMemorySize, SMEM_MM);

    // --- GEMM1: qkvz = hidden @ W_qkvz  (fp16 HMMA; bm fast) ---
    cvt_h<<<(BSz*(size_t)HID)/1024, 256>>>(hidden, p_p);
    cvt_T<<<dim3(QKVZ_N/32, HID/32), dim3(32,8)>>>(Wqkvz, r_p, HID, QKVZ_N);
    mmgemm<<<dim3(BSz/128, QKVZ_N/128), 256, SMEM_MM>>>(p_p, r_p, qkvz_p, BSz, QKVZ_N, HID);

    // --- small BA projection (split-K + reduce) ---
    gemm_ba_part<<<dim3(BSz/64, 8), 256>>>(hidden, Wba);
    gemm_ba_reduce<<<(BSz*64)/256, 256>>>();

    // --- conv + gates, chunk prep, scan, norm ---
    conv_gate<<<BSz, 256>>>(convw, dtb, Alog);
    chunk_prep<<<B_*HVv*NCH, 256, SMEM3>>>();
    scan_kernel<<<dim3(B_*HVv, 2), 512, SMEM4>>>();
    gated_norm<<<BSz, 256>>>(nw);

    // --- GEMM2: out = o @ W_out (fp16 HMMA; bm fast) ---
    cvt_h<<<(BSz*(size_t)VALUE_DIM)/1024, 256>>>(o_p, r_p);
    cvt_T<<<dim3(HID/32, VALUE_DIM/32), dim3(32,8)>>>(Wout, p_p, VALUE_DIM, HID);
    mmgemm<<<dim3(BSz/128, HID/128), 256, SMEM_MM>>>(r_p, p_p, out, BSz, HID, VALUE_DIM);
}

// round 7
// speedup vs baseline: 3.6686x; 1.3449x over previous
#include <cuda_runtime.h>
#include <cuda_bf16.h>
#include <cuda_fp16.h>
#include <math.h>
#include <stdint.h>

// ---------------- problem constants ----------------
#define B_   2
#define S_   2048
#define HID  2048
#define HKq  16
#define HVv  32
#define DKd  128
#define DVd  128
#define KC   4
#define CHUNK 64
#define NCH  (S_/CHUNK)          // 32
#define KEY_DIM 2048
#define VALUE_DIM 4096
#define CONV_DIM 8192
#define QKVZ_N 12288
#define BSz  (B_*S_)             // 4096
#define QSCALE 0.08838834764831845f   // DK^-0.5
#define SW 132                   // float4-aligned, conflict-free smem row stride

// ---------------- scratch (static device memory; no allocations) ------------
__device__ float g_qkvz[(size_t)BSz*QKVZ_N];               // [BS,12288] q|k|v|z
__device__ float g_bap[(size_t)8*BSz*64];                  // split-K partials
__device__ float g_q[(size_t)B_*HKq*S_*DKd];
__device__ float g_k[(size_t)B_*HKq*S_*DKd];
__device__ float g_v[(size_t)B_*HVv*S_*DVd];
__device__ float g_g[(size_t)B_*HVv*S_];
__device__ float g_beta[(size_t)B_*HVv*S_];
__device__ float g_gc[(size_t)B_*HVv*S_];
__device__ float g_vadj[(size_t)B_*HVv*S_*DVd];
__device__ float g_kcd[(size_t)B_*HVv*S_*DKd];
__device__ float g_attn[(size_t)B_*HVv*S_*CHUNK];
__device__ float g_o[(size_t)BSz*VALUE_DIM];

// fp16 operand buffers (reused across the two GEMMs)
__device__ __half g_p [(size_t)8388608];    // A1     / B2t
__device__ __half g_r [(size_t)25165824];   // B1t    / A2 (written by gated_norm)

__device__ __forceinline__ uint32_t smem_u32(const void* p) {
    uint32_t a;
    asm("{ .reg .u64 t; cvta.to.shared.u64 t, %1; cvt.u32.u64 %0, t; }" : "=r"(a) : "l"(p));
    return a;
}

// ---------------- fp32 -> fp16 (elementwise, float4) ----------------
__global__ void cvt_h(const float* __restrict__ X, __half* __restrict__ H) {
    size_t i = ((size_t)blockIdx.x * 256 + threadIdx.x) * 4;
    float4 v = *(const float4*)&X[i];
    __half2 h0 = __floats2half2_rn(v.x, v.y);
    __half2 h1 = __floats2half2_rn(v.z, v.w);
    uint2 hv;
    hv.x = *(uint32_t*)&h0; hv.y = *(uint32_t*)&h1;
    *(uint2*)&H[i] = hv;
}

// ---------------- fp32 [K,N] -> fp16 [N,K] transpose ----------------
__global__ void cvt_T(const float* __restrict__ W, __half* __restrict__ Ht, int K, int N) {
    __shared__ float tile[32][33];
    int n0 = blockIdx.x * 32, k0 = blockIdx.y * 32;
    int tx = threadIdx.x, ty = threadIdx.y;   // 32 x 8
#pragma unroll
    for (int j = 0; j < 32; j += 8)
        tile[ty + j][tx] = W[(size_t)(k0 + ty + j) * N + n0 + tx];
    __syncthreads();
#pragma unroll
    for (int j = 0; j < 32; j += 8)
        Ht[(size_t)(n0 + ty + j) * K + k0 + tx] = __float2half_rn(tile[tx][ty + j]);
}

// ============ fp16 HMMA GEMM: C[M,N] = A[M,K] @ Bt[N,K]^T (fp32 accum) ============
#define PSH 40
#define TEN2 (128*PSH)
#define STG1 (2*TEN2)
#define NSTG 4

__device__ __forceinline__ void mma_f16(float* c, const uint32_t* a, const uint32_t* b) {
    asm volatile("mma.sync.aligned.m16n8k16.row.col.f32.f16.f16.f32 "
                 "{%0,%1,%2,%3}, {%4,%5,%6,%7}, {%8,%9}, {%0,%1,%2,%3};"
                 : "+f"(c[0]), "+f"(c[1]), "+f"(c[2]), "+f"(c[3])
                 : "r"(a[0]), "r"(a[1]), "r"(a[2]), "r"(a[3]), "r"(b[0]), "r"(b[1]));
}
__device__ __forceinline__ void ldmx4(uint32_t* r, uint32_t addr) {
    asm volatile("ldmatrix.sync.aligned.m8n8.x4.shared.b16 {%0,%1,%2,%3}, [%4];"
                 : "=r"(r[0]), "=r"(r[1]), "=r"(r[2]), "=r"(r[3]) : "r"(addr));
}

__device__ __forceinline__ void stage_load(uint32_t sbase_b, int stage,
    const __half* a0, const __half* b0, int K, int kt, int tid)
{
    const __half* gp[2] = {a0, b0};
    uint32_t st_b = sbase_b + (uint32_t)stage * (STG1 * 2);
#pragma unroll
    for (int t = 0; t < 2; t++) {
        uint32_t tb = st_b + (uint32_t)t * (TEN2 * 2);
#pragma unroll
        for (int j = 0; j < 2; j++) {
            int idx = j * 256 + tid;
            int row = idx >> 2, c16 = idx & 3;
            uint32_t sa = tb + (uint32_t)(row * (PSH*2) + c16 * 16);
            const void* ga = gp[t] + (size_t)row * K + (size_t)kt * 32 + c16 * 8;
            asm volatile("cp.async.cg.shared.global [%0], [%1], 16;" :: "r"(sa), "l"(ga));
        }
    }
    asm volatile("cp.async.commit_group;" ::: "memory");
}

__global__ void __launch_bounds__(256, 2) mmgemm(
    const __half* __restrict__ Ah, const __half* __restrict__ Bh,
    float* __restrict__ C, int M, int N, int K)
{
    extern __shared__ __half smem[];
    uint32_t sbase = smem_u32(smem);
    int tid = threadIdx.x, lane = tid & 31, wid = tid >> 5;
    int warpM = wid >> 2, warpN = wid & 3;
    int bm = blockIdx.x, bn = blockIdx.y;
    const int T = K >> 5;

    const __half* a0 = Ah + (size_t)bm * 128 * K;
    const __half* b0 = Bh + (size_t)bn * 128 * K;

    int g = lane >> 3, lr = lane & 7;
    uint32_t aoff = (uint32_t)((warpM*64 + (g&1)*8 + lr) * PSH + (g>>1)*8);
    uint32_t boff = (uint32_t)((warpN*32 + (g>>1)*8 + lr) * PSH + (g&1)*8);

    float acc[4][4][4];
#pragma unroll
    for (int i = 0; i < 4; i++)
#pragma unroll
        for (int j = 0; j < 4; j++)
#pragma unroll
            for (int r = 0; r < 4; r++) acc[i][j][r] = 0.f;

    stage_load(sbase, 0, a0, b0, K, 0, tid);
    stage_load(sbase, 1, a0, b0, K, 1, tid);
    stage_load(sbase, 2, a0, b0, K, 2, tid);

    for (int kt = 0; kt < T; kt++) {
        int rem = T - 1 - kt;
        if (rem >= 2)      asm volatile("cp.async.wait_group 2;" ::: "memory");
        else if (rem == 1) asm volatile("cp.async.wait_group 1;" ::: "memory");
        else               asm volatile("cp.async.wait_group 0;" ::: "memory");
        __syncthreads();
        if (kt + 3 < T) stage_load(sbase, (kt + 3) % NSTG, a0, b0, K, kt + 3, tid);

        uint32_t st = sbase + (uint32_t)(kt % NSTG) * (STG1 * 2);
        uint32_t sA = st, sB = st + TEN2*2;
#pragma unroll
        for (int ks = 0; ks < 2; ks++) {
            int kk = ks * 16;
            uint32_t ah[4][4], bh[4][2];
#pragma unroll
            for (int mi = 0; mi < 4; mi++)
                ldmx4(ah[mi], sA + (aoff + mi*16*PSH + kk) * 2);
#pragma unroll
            for (int p = 0; p < 2; p++) {
                uint32_t rh[4];
                ldmx4(rh, sB + (boff + p*16*PSH + kk) * 2);
                bh[2*p][0] = rh[0]; bh[2*p][1] = rh[1];
                bh[2*p+1][0] = rh[2]; bh[2*p+1][1] = rh[3];
            }
#pragma unroll
            for (int mi = 0; mi < 4; mi++)
#pragma unroll
                for (int ni = 0; ni < 4; ni++)
                    mma_f16(acc[mi][ni], ah[mi], bh[ni]);
        }
        __syncthreads();
    }

    int rr = lane >> 2, cc = (lane & 3) * 2;
#pragma unroll
    for (int mi = 0; mi < 4; mi++) {
        int row0 = bm * 128 + warpM * 64 + mi * 16 + rr;
#pragma unroll
        for (int ni = 0; ni < 4; ni++) {
            int col = bn * 128 + warpN * 32 + ni * 8 + cc;
            float2 v0 = make_float2(acc[mi][ni][0], acc[mi][ni][1]);
            float2 v1 = make_float2(acc[mi][ni][2], acc[mi][ni][3]);
            *(float2*)&C[(size_t)row0 * N + col]       = v0;
            *(float2*)&C[(size_t)(row0 + 8) * N + col] = v1;
        }
    }
}

// ------------- BA projection split-K -> partials -------------
__global__ void gemm_ba_part(const float* __restrict__ X, const float* __restrict__ W) {
    __shared__ float Xs[64][65];
    __shared__ float Ws[64][64];
    int tid = threadIdx.x;
    int row0 = blockIdx.x * 64;
    int kbase = blockIdx.y * 256;
    int col = (tid & 15) * 4;
    int r0 = (tid >> 4) * 4;
    float acc[4][4] = {};
    for (int k0 = kbase; k0 < kbase + 256; k0 += 64) {
#pragma unroll
        for (int j = 0; j < 16; j++) {
            int idx = j * 256 + tid;
            int r = idx >> 6, kk = idx & 63;
            Xs[r][kk] = X[(size_t)(row0 + r) * HID + k0 + kk];
        }
#pragma unroll
        for (int j = 0; j < 16; j++) {
            int idx = j * 256 + tid;
            int kk = idx >> 6, c = idx & 63;
            Ws[kk][c] = W[(size_t)(k0 + kk) * 64 + c];
        }
        __syncthreads();
#pragma unroll 8
        for (int kk = 0; kk < 64; kk++) {
            float4 b = *(float4*)&Ws[kk][col];
#pragma unroll
            for (int r = 0; r < 4; r++) {
                float a = Xs[r0 + r][kk];
                acc[r][0] += a*b.x; acc[r][1] += a*b.y; acc[r][2] += a*b.z; acc[r][3] += a*b.w;
            }
        }
        __syncthreads();
    }
    float* dst = g_bap + (size_t)blockIdx.y * BSz * 64;
#pragma unroll
    for (int r = 0; r < 4; r++)
        *(float4*)&dst[(size_t)(row0 + r0 + r) * 64 + col] =
            make_float4(acc[r][0], acc[r][1], acc[r][2], acc[r][3]);
}

// -------- conv + silu + l2norm + head transpose + gates (+ba reduce fused) --------
__global__ void conv_gate(const float* __restrict__ cw, const float* __restrict__ dtb,
                          const float* __restrict__ Alog) {
    int bs = blockIdx.x;
    int b = bs / S_, s = bs % S_;
    int tid = threadIdx.x;
    __shared__ float cs[CONV_DIM];
    __shared__ float hsum[32];
    const float* base = g_qkvz + (size_t)bs * QKVZ_N;

    for (int c = tid; c < CONV_DIM; c += 256) {
        float w0 = cw[c*4+0], w1 = cw[c*4+1], w2 = cw[c*4+2], w3 = cw[c*4+3];
        float acc = base[c] * w3;
        if (s >= 1) acc += base[c - (size_t)QKVZ_N] * w2;
        if (s >= 2) acc += base[c - (size_t)2*QKVZ_N] * w1;
        if (s >= 3) acc += base[c - (size_t)3*QKVZ_N] * w0;
        cs[c] = acc / (1.f + __expf(-acc));
    }
    __syncthreads();
    int warp = tid >> 5, lane = tid & 31;
    for (int h = warp; h < 32; h += 8) {
        float ss = 0.f;
        for (int d = lane; d < 128; d += 32) { float v = cs[h*128 + d]; ss += v * v; }
#pragma unroll
        for (int o = 16; o; o >>= 1) ss += __shfl_xor_sync(~0u, ss, o);
        if (!lane) hsum[h] = rsqrtf(ss + 1e-6f);
    }
    __syncthreads();
    for (int c = tid; c < KEY_DIM; c += 256) {
        int h = c >> 7, d = c & 127;
        g_q[(((size_t)b*HKq + h)*S_ + s)*DKd + d] = cs[c] * hsum[h] * QSCALE;
    }
    for (int c = tid; c < KEY_DIM; c += 256) {
        int h = c >> 7, d = c & 127;
        g_k[(((size_t)b*HKq + h)*S_ + s)*DKd + d] = cs[KEY_DIM + c] * hsum[16 + h];
    }
    for (int c = tid; c < VALUE_DIM; c += 256) {
        int h = c >> 7, d = c & 127;
        g_v[(((size_t)b*HVv + h)*S_ + s)*DVd + d] = cs[2*KEY_DIM + c];
    }
    if (tid < 64) {
        float bb = 0.f;
#pragma unroll
        for (int p = 0; p < 8; p++) bb += g_bap[(size_t)p * BSz * 64 + (size_t)bs * 64 + tid];
        if (tid < 32) {
            g_beta[((size_t)b*HVv + tid)*S_ + s] = 1.f / (1.f + expf(-bb));
        } else {
            int h = tid - 32;
            float a = bb + dtb[h];
            float sp = (a > 20.f) ? a : log1pf(expf(a));
            g_g[((size_t)b*HVv + h)*S_ + s] = -expf(Alog[h]) * sp;
        }
    }
}

// -------- per-(b,h,chunk) intra-chunk quantities (register-tiled float4) --------
__global__ void __launch_bounds__(256, 1) chunk_prep() {
    extern __shared__ float sm[];
    float* q_s  = sm;                      // 64*SW
    float* k_s  = q_s  + 64*SW;
    float* vb_s = k_s  + 64*SW;
    float* A_s  = vb_s + 64*SW;            // 64*64
    float* T_s  = A_s  + 64*64;            // 64*65
    __shared__ float gc_s[64], beta_s[64], kbe_s[64];

    int blk = blockIdx.x;
    int n = blk & 31, h = (blk >> 5) & 31, b = blk >> 10;
    int hq = h >> 1;
    int tid = threadIdx.x;

    size_t qk_off = (((size_t)b*HKq + hq)*S_ + (size_t)n*CHUNK) * DKd;
    size_t v_off  = (((size_t)b*HVv + h )*S_ + (size_t)n*CHUNK) * DVd;
    size_t gb_off = ((size_t)b*HVv + h)*S_ + (size_t)n*CHUNK;

    if (tid < 64) { gc_s[tid] = g_g[gb_off + tid]; beta_s[tid] = g_beta[gb_off + tid]; }
    __syncthreads();
    if (tid == 0) { for (int i = 1; i < 64; i++) gc_s[i] += gc_s[i - 1]; }
    __syncthreads();
    if (tid < 64) {
        g_gc[gb_off + tid] = gc_s[tid];
        kbe_s[tid] = beta_s[tid] * expf(gc_s[tid]);
    }
    // vectorized smem fill
    for (int idx = tid; idx < 2048; idx += 256) {
        int r = idx >> 5, d = (idx & 31) * 4;
        float4 qv = *(const float4*)&g_q[qk_off + (size_t)r*128 + d];
        float4 kv = *(const float4*)&g_k[qk_off + (size_t)r*128 + d];
        float4 vv = *(const float4*)&g_v[v_off  + (size_t)r*128 + d];
        float be = beta_s[r];
        vv.x *= be; vv.y *= be; vv.z *= be; vv.w *= be;
        *(float4*)&q_s [r*SW + d] = qv;
        *(float4*)&k_s [r*SW + d] = kv;
        *(float4*)&vb_s[r*SW + d] = vv;
    }
    __syncthreads();

    // A (k.k) and attn (q.k) 64x64x128 register-tiled: 16x16 threads, 4x4 each
    {
        int jt = tid & 15, ct = tid >> 4;
        int j0 = jt * 4, c0 = ct * 4;
        float aa[4][4] = {}, aq[4][4] = {};
        for (int dk = 0; dk < 128; dk += 4) {
            float4 kj[4], kc[4], qc[4];
#pragma unroll
            for (int x = 0; x < 4; x++) kj[x] = *(float4*)&k_s[(j0+x)*SW + dk];
#pragma unroll
            for (int x = 0; x < 4; x++) kc[x] = *(float4*)&k_s[(c0+x)*SW + dk];
#pragma unroll
            for (int x = 0; x < 4; x++) qc[x] = *(float4*)&q_s[(c0+x)*SW + dk];
#pragma unroll
            for (int ci = 0; ci < 4; ci++)
#pragma unroll
                for (int ji = 0; ji < 4; ji++) {
                    aa[ci][ji] += kc[ci].x*kj[ji].x + kc[ci].y*kj[ji].y
                                + kc[ci].z*kj[ji].z + kc[ci].w*kj[ji].w;
                    aq[ci][ji] += qc[ci].x*kj[ji].x + qc[ci].y*kj[ji].y
                                + qc[ci].z*kj[ji].z + qc[ci].w*kj[ji].w;
                }
        }
        size_t at_off = gb_off * CHUNK;
#pragma unroll
        for (int ci = 0; ci < 4; ci++)
#pragma unroll
            for (int ji = 0; ji < 4; ji++) {
                int c = c0 + ci, j = j0 + ji;
                float e = __expf(gc_s[c] - gc_s[j]);
                A_s[c*64 + j] = (j < c) ? aa[ci][ji] * beta_s[c] * e : 0.f;
                g_attn[at_off + c*64 + j] = (j <= c) ? aq[ci][ji] * e : 0.f;
            }
    }
    __syncthreads();

    // T = (I+A)^{-1}, forward substitution, one thread per column
    if (tid < 64) {
        int col = tid;
        for (int c = 0; c < 64; c++) {
            float ssum = (c == col) ? 1.f : 0.f;
            for (int j = col; j < c; j++) ssum -= A_s[c*64 + j] * T_s[j*65 + col];
            T_s[c*65 + col] = (c >= col) ? ssum : 0.f;
        }
    }
    __syncthreads();

    // v_adj = T@vb, kcd = T@(k*kbe): warp per 8-row block, lane per 4 dims
    {
        int ct8 = tid >> 5, lane = tid & 31;
        int c0 = ct8 * 8, d0 = lane * 4;
        float av[8][4] = {}, ak[8][4] = {};
        int jmax = c0 + 8;                 // T is zero above diagonal
        for (int j = 0; j < jmax; j++) {
            float4 vv = *(float4*)&vb_s[j*SW + d0];
            float4 kk = *(float4*)&k_s [j*SW + d0];
            float kb = kbe_s[j];
            kk.x *= kb; kk.y *= kb; kk.z *= kb; kk.w *= kb;
#pragma unroll
            for (int ci = 0; ci < 8; ci++) {
                float t = T_s[(c0+ci)*65 + j];
                av[ci][0] += t*vv.x; av[ci][1] += t*vv.y; av[ci][2] += t*vv.z; av[ci][3] += t*vv.w;
                ak[ci][0] += t*kk.x; ak[ci][1] += t*kk.y; ak[ci][2] += t*kk.z; ak[ci][3] += t*kk.w;
            }
        }
        size_t kcd_off = (((size_t)b*HVv + h)*S_ + (size_t)n*CHUNK) * DKd;
#pragma unroll
        for (int ci = 0; ci < 8; ci++) {
            *(float4*)&g_vadj[v_off  + (size_t)(c0+ci)*128 + d0] =
                make_float4(av[ci][0], av[ci][1], av[ci][2], av[ci][3]);
            *(float4*)&g_kcd [kcd_off + (size_t)(c0+ci)*128 + d0] =
                make_float4(ak[ci][0], ak[ci][1], ak[ci][2], ak[ci][3]);
        }
    }
}

// -------- sequential scan over chunks; 512 threads, dv-tile 64, grid (64,2) --------
__global__ void __launch_bounds__(512, 1) scan_kernel() {
    extern __shared__ float sm[];
    float* q_s    = sm;                    // 64*SW
    float* k_s    = q_s   + 64*SW;
    float* kcd_s  = k_s   + 64*SW;
    float* attn_s = kcd_s + 64*SW;         // 4096
    float* vadj_s = attn_s + 4096;         // 4096
    float* vnew_s = vadj_s + 4096;         // 4096
    float* vek_s  = vnew_s + 4096;         // 4096
    float* st     = vek_s  + 4096;         // 128*64
    __shared__ float gc_s[64], eg_s[64], ek_s[64];

    int bh = blockIdx.x, dvt = blockIdx.y;
    int b = bh >> 5, h = bh & 31, hq = h >> 1;
    int tid = threadIdx.x;
    int dv0 = (tid & 15) * 4;              // 4 consecutive dv
    int grp = tid >> 4;                    // 0..31

    for (int i = tid; i < 128 * 64; i += 512) st[i] = 0.f;

    for (int n = 0; n < NCH; n++) {
        size_t qk_off = (((size_t)b*HKq + hq)*S_ + (size_t)n*CHUNK) * DKd;
        size_t kv_off = (((size_t)b*HVv + h )*S_ + (size_t)n*CHUNK) * DKd;
        size_t gb_off = ((size_t)b*HVv + h)*S_ + (size_t)n*CHUNK;
        __syncthreads();
        for (int idx = tid; idx < 2048; idx += 512) {
            int r = idx >> 5, d = (idx & 31) * 4;
            *(float4*)&q_s  [r*SW + d] = *(const float4*)&g_q  [qk_off + (size_t)r*128 + d];
            *(float4*)&k_s  [r*SW + d] = *(const float4*)&g_k  [qk_off + (size_t)r*128 + d];
            *(float4*)&kcd_s[r*SW + d] = *(const float4*)&g_kcd[kv_off + (size_t)r*128 + d];
        }
        for (int idx = tid; idx < 1024; idx += 512)
            *(float4*)&attn_s[idx*4] = *(const float4*)&g_attn[gb_off*CHUNK + idx*4];
        for (int idx = tid; idx < 1024; idx += 512) {
            int c = idx >> 4, d = (idx & 15) * 4;
            *(float4*)&vadj_s[c*64 + d] =
                *(const float4*)&g_vadj[kv_off + (size_t)c*128 + dvt*64 + d];
        }
        if (tid < 64) { float gv = g_gc[gb_off + tid]; gc_s[tid] = gv; eg_s[tid] = expf(gv); }
        __syncthreads();
        if (tid < 64) ek_s[tid] = expf(gc_s[63] - gc_s[tid]);

        // v_new = v_adj - kcd @ state ; vek = v_new * ek[c]
        {
            int c0 = grp * 2;
            float a0[4], a1[4];
            *(float4*)a0 = *(float4*)&vadj_s[c0*64 + dv0];
            *(float4*)a1 = *(float4*)&vadj_s[(c0+1)*64 + dv0];
            for (int dk = 0; dk < 128; dk++) {
                float4 s4 = *(float4*)&st[dk*64 + dv0];
                float k0v = kcd_s[c0*SW + dk], k1v = kcd_s[(c0+1)*SW + dk];
                a0[0] -= k0v*s4.x; a0[1] -= k0v*s4.y; a0[2] -= k0v*s4.z; a0[3] -= k0v*s4.w;
                a1[0] -= k1v*s4.x; a1[1] -= k1v*s4.y; a1[2] -= k1v*s4.z; a1[3] -= k1v*s4.w;
            }
            *(float4*)&vnew_s[c0*64 + dv0]     = *(float4*)a0;
            *(float4*)&vnew_s[(c0+1)*64 + dv0] = *(float4*)a1;
            float e0 = ek_s[c0], e1 = ek_s[c0+1];
            *(float4*)&vek_s[c0*64 + dv0] =
                make_float4(a0[0]*e0, a0[1]*e0, a0[2]*e0, a0[3]*e0);
            *(float4*)&vek_s[(c0+1)*64 + dv0] =
                make_float4(a1[0]*e1, a1[1]*e1, a1[2]*e1, a1[3]*e1);
        }
        __syncthreads();

        // o = (q*exp(gc)) @ state + attn @ v_new
        {
            int c0 = grp * 2;
            float o0[4] = {}, o1[4] = {};
            for (int dk = 0; dk < 128; dk++) {
                float4 s4 = *(float4*)&st[dk*64 + dv0];
                float q0 = q_s[c0*SW + dk], q1 = q_s[(c0+1)*SW + dk];
                o0[0] += q0*s4.x; o0[1] += q0*s4.y; o0[2] += q0*s4.z; o0[3] += q0*s4.w;
                o1[0] += q1*s4.x; o1[1] += q1*s4.y; o1[2] += q1*s4.z; o1[3] += q1*s4.w;
            }
            float e0 = eg_s[c0], e1 = eg_s[c0+1];
#pragma unroll
            for (int x = 0; x < 4; x++) { o0[x] *= e0; o1[x] *= e1; }
            for (int j = 0; j < 64; j++) {
                float4 v4 = *(float4*)&vnew_s[j*64 + dv0];
                float a0v = attn_s[c0*64 + j], a1v = attn_s[(c0+1)*64 + j];
                o0[0] += a0v*v4.x; o0[1] += a0v*v4.y; o0[2] += a0v*v4.z; o0[3] += a0v*v4.w;
                o1[0] += a1v*v4.x; o1[1] += a1v*v4.y; o1[2] += a1v*v4.z; o1[3] += a1v*v4.w;
            }
            size_t ob = ((size_t)b*S_ + (size_t)n*CHUNK) * VALUE_DIM + (size_t)h*DVd + dvt*64 + dv0;
            *(float4*)&g_o[ob + (size_t)c0*VALUE_DIM]     = *(float4*)o0;
            *(float4*)&g_o[ob + (size_t)(c0+1)*VALUE_DIM] = *(float4*)o1;
        }

        // state = state*exp(g_last) + k^T @ vek
        {
            int dk0 = grp * 4;
            float egl = eg_s[63];
            float sa[4][4];
#pragma unroll
            for (int i = 0; i < 4; i++) {
                float4 s4 = *(float4*)&st[(dk0+i)*64 + dv0];
                sa[i][0] = s4.x*egl; sa[i][1] = s4.y*egl; sa[i][2] = s4.z*egl; sa[i][3] = s4.w*egl;
            }
            for (int c = 0; c < 64; c++) {
                float4 v4 = *(float4*)&vek_s[c*64 + dv0];
                float4 k4 = *(float4*)&k_s[c*SW + dk0];
                sa[0][0] += k4.x*v4.x; sa[0][1] += k4.x*v4.y; sa[0][2] += k4.x*v4.z; sa[0][3] += k4.x*v4.w;
                sa[1][0] += k4.y*v4.x; sa[1][1] += k4.y*v4.y; sa[1][2] += k4.y*v4.z; sa[1][3] += k4.y*v4.w;
                sa[2][0] += k4.z*v4.x; sa[2][1] += k4.z*v4.y; sa[2][2] += k4.z*v4.z; sa[2][3] += k4.z*v4.w;
                sa[3][0] += k4.w*v4.x; sa[3][1] += k4.w*v4.y; sa[3][2] += k4.w*v4.z; sa[3][3] += k4.w*v4.w;
            }
            __syncthreads();
#pragma unroll
            for (int i = 0; i < 4; i++)
                *(float4*)&st[(dk0+i)*64 + dv0] =
                    make_float4(sa[i][0], sa[i][1], sa[i][2], sa[i][3]);
        }
    }
}

// -------- gated RMSNorm -> fp16 directly into GEMM2 A buffer --------
__global__ void gated_norm(const float* __restrict__ nw) {
    int bs = blockIdx.x;
    int warp = threadIdx.x >> 5, lane = threadIdx.x & 31;
    for (int h = warp; h < HVv; h += 8) {
        size_t off = (size_t)bs * VALUE_DIM + (size_t)h * DVd;
        float4 v = ((float4*)(g_o + off))[lane];
        float ss = v.x*v.x + v.y*v.y + v.z*v.z + v.w*v.w;
#pragma unroll
        for (int o = 16; o; o >>= 1) ss += __shfl_xor_sync(~0u, ss, o);
        float r = rsqrtf(ss / 128.f + 1e-6f);
        size_t zoff = (size_t)bs * QKVZ_N + 2*KEY_DIM + VALUE_DIM + (size_t)h * DVd;
        float4 z = ((const float4*)(g_qkvz + zoff))[lane];
        float4 w = ((const float4*)nw)[lane];
        float r0 = v.x * r * w.x * (z.x / (1.f + expf(-z.x)));
        float r1 = v.y * r * w.y * (z.y / (1.f + expf(-z.y)));
        float r2 = v.z * r * w.z * (z.z / (1.f + expf(-z.z)));
        float r3 = v.w * r * w.w * (z.w / (1.f + expf(-z.w)));
        __half2 h0 = __floats2half2_rn(r0, r1);
        __half2 h1 = __floats2half2_rn(r2, r3);
        uint2 hv; hv.x = *(uint32_t*)&h0; hv.y = *(uint32_t*)&h1;
        ((uint2*)(g_r + off))[lane] = hv;
    }
}

// ---------------- launcher ----------------
extern "C" void kernel_launch(void* const* d_in, const int* in_sizes, int n_in,
                              void* d_out, int out_size) {
    const float* hidden = (const float*)d_in[0];
    const float* Wqkvz  = (const float*)d_in[1];
    const float* Wba    = (const float*)d_in[2];
    const float* convw  = (const float*)d_in[3];
    const float* dtb    = (const float*)d_in[4];
    const float* Alog   = (const float*)d_in[5];
    const float* nw     = (const float*)d_in[6];
    const float* Wout   = (const float*)d_in[7];
    float* out = (float*)d_out;

    float *qkvz_p;
    __half *p_p, *r_p;
    cudaGetSymbolAddress((void**)&qkvz_p, g_qkvz);
    cudaGetSymbolAddress((void**)&p_p, g_p);
    cudaGetSymbolAddress((void**)&r_p, g_r);

    const int SMEM3 = (3*64*SW + 64*64 + 64*65) * 4;                     // 134.4KB
    const int SMEM4 = (3*64*SW + 4*4096 + 128*64) * 4;                   // 199.7KB
    const int SMEM_MM = NSTG * STG1 * 2;                                 // 81920
    cudaFuncSetAttribute(chunk_prep, cudaFuncAttributeMaxDynamicSharedMemorySize, SMEM3);
    cudaFuncSetAttribute(scan_kernel, cudaFuncAttributeMaxDynamicSharedMemorySize, SMEM4);
    cudaFuncSetAttribute(mmgemm, cudaFuncAttributeMaxDynamicSharedMemorySize, SMEM_MM);

    // --- GEMM1: qkvz = hidden @ W_qkvz ---
    cvt_h<<<(BSz*(size_t)HID)/1024, 256>>>(hidden, p_p);
    cvt_T<<<dim3(QKVZ_N/32, HID/32), dim3(32,8)>>>(Wqkvz, r_p, HID, QKVZ_N);
    mmgemm<<<dim3(BSz/128, QKVZ_N/128), 256, SMEM_MM>>>(p_p, r_p, qkvz_p, BSz, QKVZ_N, HID);

    // --- BA projection (split-K; reduce fused into conv_gate) ---
    gemm_ba_part<<<dim3(BSz/64, 8), 256>>>(hidden, Wba);

    // --- conv + gates, chunk prep, scan, norm ---
    conv_gate<<<BSz, 256>>>(convw, dtb, Alog);
    chunk_prep<<<B_*HVv*NCH, 256, SMEM3>>>();
    scan_kernel<<<dim3(B_*HVv, 2), 512, SMEM4>>>();
    gated_norm<<<BSz, 256>>>(nw);

    // --- GEMM2: out = o @ W_out (A written fp16 by gated_norm) ---
    cvt_T<<<dim3(HID/32, VALUE_DIM/32), dim3(32,8)>>>(Wout, p_p, VALUE_DIM, HID);
    mmgemm<<<dim3(BSz/128, HID/128), 256, SMEM_MM>>>(r_p, p_p, out, BSz, HID, VALUE_DIM);
}